// round 1
// baseline (speedup 1.0000x reference)
#include <cuda_runtime.h>
#include <cstdint>

// ---------------------------------------------------------------------------
// MultiheadRCDA: row-column decoupled attention.
// E=256, NH=8, HD=32, N=8, L=300, H=W=96.
//
// Pipeline:
//  1. mean-reduce key_row over H -> krm[n,w,256]; key_col over W -> kcm[n,h,256]
//     (mean commutes with the affine projection -> huge FLOP saving)
//  2. GEMMs: q_row, q_col (scaled), krm, kcm, value projections
//  3. scores + softmax (row over w, col over h), per (n,l), warp-per-head
//  4. attend: out[n,l,e,d] = sum_h acol[h] * sum_w arow[w] * v[n,h,w,e*32+d]
//  5. out_proj GEMM into d_out, rows ordered (l*8+n)
// ---------------------------------------------------------------------------

#define NB   8
#define LL   300
#define HH   96
#define WW   96
#define EE   256
#define NHD  8
#define HDD  32

// scratch (device globals; allocation-free kernel_launch)
__device__ float g_krm[NB*WW*EE];          // mean over H of key_row
__device__ float g_kcm[NB*HH*EE];          // mean over W of key_col
__device__ float g_qr [NB*LL*EE];
__device__ float g_qc [NB*LL*EE];
__device__ float g_krp[NB*WW*EE];
__device__ float g_kcp[NB*HH*EE];
__device__ float g_vp [NB*HH*WW*EE];       // 75.5 MB
__device__ float g_arow[NB*NHD*LL*WW];
__device__ float g_acol[NB*NHD*LL*HH];
__device__ float g_attn[LL*NB*EE];         // rows ordered l*8+n

// ---------------------------------------------------------------------------
// K1: mean reductions
// grid (96, 2, 8), block 256 (one thread per channel e)
// ---------------------------------------------------------------------------
__global__ void mean_kernel(const float* __restrict__ key_row,
                            const float* __restrict__ key_col,
                            float* __restrict__ krm,
                            float* __restrict__ kcm)
{
    int idx = blockIdx.x;        // w (for krm) or h (for kcm)
    int which = blockIdx.y;
    int n = blockIdx.z;
    int e = threadIdx.x;
    float s = 0.f;
    if (which == 0) {
        // krm[n, w=idx, e] = mean_h key_row[n,h,w,e]
        const float* p = key_row + ((size_t)n*HH*WW + idx) * EE + e;
        #pragma unroll 8
        for (int h = 0; h < HH; ++h) s += p[(size_t)h*WW*EE];
        krm[(n*WW + idx)*EE + e] = s * (1.f/96.f);
    } else {
        // kcm[n, h=idx, e] = mean_w key_col[n,h,w,e]
        const float* p = key_col + ((size_t)(n*HH + idx)*WW) * EE + e;
        #pragma unroll 8
        for (int w = 0; w < WW; ++w) s += p[(size_t)w*EE];
        kcm[(n*HH + idx)*EE + e] = s * (1.f/96.f);
    }
}

// ---------------------------------------------------------------------------
// K2: generic GEMM  Y[M,256] = (X[M,256] @ W[256,256]^T + bias) * scale
// W row-major [out,in]. Tiled 64x64, BK=16, 256 threads, 4x4 per thread.
// ---------------------------------------------------------------------------
__global__ void gemm_bias_kernel(const float* __restrict__ X,
                                 const float* __restrict__ W,
                                 const float* __restrict__ bias,
                                 float* __restrict__ Y,
                                 int M, float scale)
{
    __shared__ __align__(16) float As[16][64];
    __shared__ __align__(16) float Bs[16][64];

    int tx = threadIdx.x;
    int row0 = blockIdx.y * 64;
    int col0 = blockIdx.x * 64;
    int tm = (tx >> 4) * 4;       // 0..60
    int tn = (tx & 15) * 4;       // 0..60

    float acc[4][4] = {};

    int lm = tx >> 2;             // 0..63 (row/col within tile for loads)
    int kq = (tx & 3) * 4;        // 0,4,8,12

    for (int k0 = 0; k0 < 256; k0 += 16) {
        // load A tile (guard rows)
        {
            int gr = row0 + lm;
            float4 v = make_float4(0.f,0.f,0.f,0.f);
            if (gr < M) v = *(const float4*)(X + (size_t)gr*256 + k0 + kq);
            As[kq+0][lm] = v.x; As[kq+1][lm] = v.y;
            As[kq+2][lm] = v.z; As[kq+3][lm] = v.w;
        }
        // load B tile (always in range: col0+lm < 256)
        {
            float4 v = *(const float4*)(W + (size_t)(col0 + lm)*256 + k0 + kq);
            Bs[kq+0][lm] = v.x; Bs[kq+1][lm] = v.y;
            Bs[kq+2][lm] = v.z; Bs[kq+3][lm] = v.w;
        }
        __syncthreads();
        #pragma unroll
        for (int k = 0; k < 16; ++k) {
            float4 a = *(const float4*)(&As[k][tm]);
            float4 b = *(const float4*)(&Bs[k][tn]);
            acc[0][0] += a.x*b.x; acc[0][1] += a.x*b.y; acc[0][2] += a.x*b.z; acc[0][3] += a.x*b.w;
            acc[1][0] += a.y*b.x; acc[1][1] += a.y*b.y; acc[1][2] += a.y*b.z; acc[1][3] += a.y*b.w;
            acc[2][0] += a.z*b.x; acc[2][1] += a.z*b.y; acc[2][2] += a.z*b.z; acc[2][3] += a.z*b.w;
            acc[3][0] += a.w*b.x; acc[3][1] += a.w*b.y; acc[3][2] += a.w*b.z; acc[3][3] += a.w*b.w;
        }
        __syncthreads();
    }

    float4 b4 = *(const float4*)(bias + col0 + tn);
    #pragma unroll
    for (int i = 0; i < 4; ++i) {
        int gr = row0 + tm + i;
        if (gr < M) {
            float4 r;
            r.x = (acc[i][0] + b4.x) * scale;
            r.y = (acc[i][1] + b4.y) * scale;
            r.z = (acc[i][2] + b4.z) * scale;
            r.w = (acc[i][3] + b4.w) * scale;
            *(float4*)(Y + (size_t)gr*256 + col0 + tn) = r;
        }
    }
}

// ---------------------------------------------------------------------------
// K3: scores + softmax. One block per (n,l); computes all 8 heads over 96 keys.
// qp rows: n*300+l; kp rows: n*96+x. aout[((n*8+e)*300+l)*96 + x]
// ---------------------------------------------------------------------------
__global__ void scores_kernel(const float* __restrict__ qp,
                              const float* __restrict__ kp,
                              float* __restrict__ aout)
{
    __shared__ __align__(16) float q_sh[256];
    __shared__ float sc[768];

    int nl = blockIdx.x;
    int n = nl / LL;
    int l = nl - n * LL;
    int tid = threadIdx.x;

    q_sh[tid] = qp[(size_t)nl*256 + tid];
    __syncthreads();

    #pragma unroll
    for (int it = 0; it < 3; ++it) {
        int idx = it*256 + tid;     // 0..767
        int e = idx / 96;
        int x = idx - e * 96;
        const float4* qq = (const float4*)(q_sh + e*32);
        const float4* kk = (const float4*)(kp + ((size_t)(n*96 + x))*256 + e*32);
        float s = 0.f;
        #pragma unroll
        for (int i = 0; i < 8; ++i) {
            float4 q4 = qq[i], k4 = kk[i];
            s += q4.x*k4.x + q4.y*k4.y + q4.z*k4.z + q4.w*k4.w;
        }
        sc[idx] = s;
    }
    __syncthreads();

    // warp per head softmax over 96
    int wid = tid >> 5, lane = tid & 31;
    float v0 = sc[wid*96 + lane];
    float v1 = sc[wid*96 + 32 + lane];
    float v2 = sc[wid*96 + 64 + lane];
    float m = fmaxf(v0, fmaxf(v1, v2));
    #pragma unroll
    for (int off = 16; off > 0; off >>= 1)
        m = fmaxf(m, __shfl_xor_sync(0xffffffffu, m, off));
    float e0 = __expf(v0 - m), e1 = __expf(v1 - m), e2 = __expf(v2 - m);
    float s = e0 + e1 + e2;
    #pragma unroll
    for (int off = 16; off > 0; off >>= 1)
        s += __shfl_xor_sync(0xffffffffu, s, off);
    float inv = 1.f / s;
    float* out = aout + (((size_t)(n*8 + wid))*LL + l)*96;
    out[lane]      = e0 * inv;
    out[lane + 32] = e1 * inv;
    out[lane + 64] = e2 * inv;
}

// ---------------------------------------------------------------------------
// K4: attend. Block = (l-tile of 32, head e, batch n); 256 threads.
// thread: l = tid>>3 (0..31), dg = tid&7 -> d = dg*4..dg*4+3
// out[n,l,e,d] = sum_h acol[l,h] * sum_w arow[l,w] * v[n,h,w,e*32+d]
// Stores to g_attn with row ordering (l*8+n) for the final out_proj GEMM.
// ---------------------------------------------------------------------------
__global__ void attend_kernel(const float* __restrict__ arow,
                              const float* __restrict__ acol,
                              const float* __restrict__ vp,
                              float* __restrict__ attn)
{
    __shared__ __align__(16) float arow_s[32*96];
    __shared__ __align__(16) float acol_s[32*96];
    __shared__ __align__(16) float v_s[96*32];

    int lt = blockIdx.x;
    int e  = blockIdx.y;
    int n  = blockIdx.z;
    int tid = threadIdx.x;
    int l  = tid >> 3;
    int dg = tid & 7;

    size_t base_a = ((size_t)(n*8 + e)) * LL * 96;
    for (int i = tid; i < 32*96; i += 256) {
        int ll = i / 96, x = i - ll*96;
        int lg = lt*32 + ll;
        float ar = 0.f, ac = 0.f;
        if (lg < LL) {
            ar = arow[base_a + (size_t)lg*96 + x];
            ac = acol[base_a + (size_t)lg*96 + x];
        }
        arow_s[i] = ar; acol_s[i] = ac;
    }

    float acc0 = 0.f, acc1 = 0.f, acc2 = 0.f, acc3 = 0.f;
    const float4* ar4 = (const float4*)(arow_s + l*96);

    for (int h = 0; h < HH; ++h) {
        __syncthreads();
        const float* vbase = vp + ((size_t)(n*HH + h))*WW*EE + e*HDD;
        #pragma unroll
        for (int i = tid; i < 96*32; i += 256) {
            int w = i >> 5, d = i & 31;
            v_s[i] = vbase[(size_t)w*EE + d];
        }
        __syncthreads();

        float ach = acol_s[l*96 + h];
        const float4* vs4 = (const float4*)v_s;
        float s0 = 0.f, s1 = 0.f, s2 = 0.f, s3 = 0.f;
        #pragma unroll 6
        for (int w4 = 0; w4 < 24; ++w4) {
            float4 a = ar4[w4];
            float4 u;
            u = vs4[(w4*4 + 0)*8 + dg];
            s0 += a.x*u.x; s1 += a.x*u.y; s2 += a.x*u.z; s3 += a.x*u.w;
            u = vs4[(w4*4 + 1)*8 + dg];
            s0 += a.y*u.x; s1 += a.y*u.y; s2 += a.y*u.z; s3 += a.y*u.w;
            u = vs4[(w4*4 + 2)*8 + dg];
            s0 += a.z*u.x; s1 += a.z*u.y; s2 += a.z*u.z; s3 += a.z*u.w;
            u = vs4[(w4*4 + 3)*8 + dg];
            s0 += a.w*u.x; s1 += a.w*u.y; s2 += a.w*u.z; s3 += a.w*u.w;
        }
        acc0 += ach*s0; acc1 += ach*s1; acc2 += ach*s2; acc3 += ach*s3;
    }

    int lg = lt*32 + l;
    if (lg < LL) {
        float4 r = make_float4(acc0, acc1, acc2, acc3);
        *(float4*)(attn + ((size_t)(lg*NB + n))*EE + e*HDD + dg*4) = r;
    }
}

// ---------------------------------------------------------------------------
// launch
// ---------------------------------------------------------------------------
static inline float* sym_ptr(const void* sym)
{
    void* p = nullptr;
    cudaGetSymbolAddress(&p, sym);
    return (float*)p;
}

extern "C" void kernel_launch(void* const* d_in, const int* in_sizes, int n_in,
                              void* d_out, int out_size)
{
    const float* query_row = (const float*)d_in[0];
    const float* query_col = (const float*)d_in[1];
    const float* key_row   = (const float*)d_in[2];
    const float* key_col   = (const float*)d_in[3];
    const float* value     = (const float*)d_in[4];
    const float* ipw       = (const float*)d_in[5];
    const float* ipb       = (const float*)d_in[6];
    const float* opw       = (const float*)d_in[7];
    const float* opb       = (const float*)d_in[8];
    float* out = (float*)d_out;

    float* krm  = sym_ptr(g_krm);
    float* kcm  = sym_ptr(g_kcm);
    float* qr   = sym_ptr(g_qr);
    float* qc   = sym_ptr(g_qc);
    float* krp  = sym_ptr(g_krp);
    float* kcp  = sym_ptr(g_kcp);
    float* vp   = sym_ptr(g_vp);
    float* arow = sym_ptr(g_arow);
    float* acol = sym_ptr(g_acol);
    float* attn = sym_ptr(g_attn);

    const float scale = 0.17677669529663687f;   // 32^-0.5

    // 1. means
    mean_kernel<<<dim3(96, 2, NB), 256>>>(key_row, key_col, krm, kcm);

    // 2. projections
    {
        dim3 blk(256);
        // q_row: M = 8*300 = 2400
        gemm_bias_kernel<<<dim3(4, (2400+63)/64), blk>>>(query_row, ipw + 0*EE*EE, ipb + 0*EE, qr, 2400, scale);
        gemm_bias_kernel<<<dim3(4, (2400+63)/64), blk>>>(query_col, ipw + 1*EE*EE, ipb + 1*EE, qc, 2400, scale);
        // k projections on the reduced tensors: M = 8*96 = 768
        gemm_bias_kernel<<<dim3(4, 768/64), blk>>>(krm, ipw + 2*EE*EE, ipb + 2*EE, krp, 768, 1.f);
        gemm_bias_kernel<<<dim3(4, 768/64), blk>>>(kcm, ipw + 3*EE*EE, ipb + 3*EE, kcp, 768, 1.f);
        // v projection: M = 8*96*96 = 73728
        gemm_bias_kernel<<<dim3(4, 73728/64), blk>>>(value, ipw + 4*EE*EE, ipb + 4*EE, vp, 73728, 1.f);
    }

    // 3. scores + softmax
    scores_kernel<<<NB*LL, 256>>>(qr, krp, arow);
    scores_kernel<<<NB*LL, 256>>>(qc, kcp, acol);

    // 4. attend
    attend_kernel<<<dim3(10, NHD, NB), 256>>>(arow, acol, vp, attn);

    // 5. out projection -> d_out (rows l*8+n)
    gemm_bias_kernel<<<dim3(4, (2400+63)/64), 256>>>(attn, opw, opb, out, 2400, 1.f);
}

// round 2
// speedup vs baseline: 1.9857x; 1.9857x over previous
#include <cuda_runtime.h>
#include <cstdint>

// ---------------------------------------------------------------------------
// MultiheadRCDA: row-column decoupled attention.  E=256, NH=8, HD=32,
// N=8, L=300, H=W=96.
//
// Round 2: tensor cores (mma.sync m16n8k8 tf32) for the two big contractions:
//   - vproj GEMM  Y[73728,256] = X @ W^T + b      (A=X hi/lo split, W rna-tf32)
//   - attend as generated-A GEMM: out[l,d] = (acol⊗arow)[l,(h,w)] @ v[(h,w),d]
//     (A generated per k-step and split hi/lo exactly; v raw-fp32 -> HW tf32)
// Everything else stays exact fp32 scalar.
// ---------------------------------------------------------------------------

#define NB   8
#define LL   300
#define HH   96
#define WW   96
#define EE   256
#define NHD  8
#define HDD  32

// scratch (device globals; allocation-free kernel_launch)
__device__ float g_krm[NB*WW*EE];
__device__ float g_kcm[NB*HH*EE];
__device__ float g_qr [NB*LL*EE];
__device__ float g_qc [NB*LL*EE];
__device__ float g_krp[NB*WW*EE];
__device__ float g_kcp[NB*HH*EE];
__device__ float g_vp [NB*HH*WW*EE];       // 75.5 MB
__device__ float g_arow[NB*NHD*LL*WW];
__device__ float g_acol[NB*NHD*LL*HH];
__device__ float g_attn[LL*NB*EE];         // rows ordered l*8+n

__device__ __forceinline__ uint32_t f2b(float x) { return __float_as_uint(x); }

__device__ __forceinline__ void mma_tf32(float* c,
                                         uint32_t a0, uint32_t a1, uint32_t a2, uint32_t a3,
                                         uint32_t b0, uint32_t b1)
{
    asm("mma.sync.aligned.m16n8k8.row.col.f32.tf32.tf32.f32 "
        "{%0,%1,%2,%3}, {%4,%5,%6,%7}, {%8,%9}, {%0,%1,%2,%3};"
        : "+f"(c[0]), "+f"(c[1]), "+f"(c[2]), "+f"(c[3])
        : "r"(a0), "r"(a1), "r"(a2), "r"(a3), "r"(b0), "r"(b1));
}

__device__ __forceinline__ float cvt_tf32_rna(float x)
{
    uint32_t t;
    asm("cvt.rna.tf32.f32 %0, %1;" : "=r"(t) : "f"(x));
    return __uint_as_float(t);
}

// ---------------------------------------------------------------------------
// K1: mean reductions (unchanged)
// ---------------------------------------------------------------------------
__global__ void mean_kernel(const float* __restrict__ key_row,
                            const float* __restrict__ key_col,
                            float* __restrict__ krm,
                            float* __restrict__ kcm)
{
    int idx = blockIdx.x;
    int which = blockIdx.y;
    int n = blockIdx.z;
    int e = threadIdx.x;
    float s = 0.f;
    if (which == 0) {
        const float* p = key_row + ((size_t)n*HH*WW + idx) * EE + e;
        #pragma unroll 8
        for (int h = 0; h < HH; ++h) s += p[(size_t)h*WW*EE];
        krm[(n*WW + idx)*EE + e] = s * (1.f/96.f);
    } else {
        const float* p = key_col + ((size_t)(n*HH + idx)*WW) * EE + e;
        #pragma unroll 8
        for (int w = 0; w < WW; ++w) s += p[(size_t)w*EE];
        kcm[(n*HH + idx)*EE + e] = s * (1.f/96.f);
    }
}

// ---------------------------------------------------------------------------
// K2: scalar GEMM for the small exact-fp32 projections + out_proj (unchanged)
// ---------------------------------------------------------------------------
__global__ void gemm_bias_kernel(const float* __restrict__ X,
                                 const float* __restrict__ W,
                                 const float* __restrict__ bias,
                                 float* __restrict__ Y,
                                 int M, float scale)
{
    __shared__ __align__(16) float As[16][64];
    __shared__ __align__(16) float Bs[16][64];

    int tx = threadIdx.x;
    int row0 = blockIdx.y * 64;
    int col0 = blockIdx.x * 64;
    int tm = (tx >> 4) * 4;
    int tn = (tx & 15) * 4;

    float acc[4][4] = {};

    int lm = tx >> 2;
    int kq = (tx & 3) * 4;

    for (int k0 = 0; k0 < 256; k0 += 16) {
        {
            int gr = row0 + lm;
            float4 v = make_float4(0.f,0.f,0.f,0.f);
            if (gr < M) v = *(const float4*)(X + (size_t)gr*256 + k0 + kq);
            As[kq+0][lm] = v.x; As[kq+1][lm] = v.y;
            As[kq+2][lm] = v.z; As[kq+3][lm] = v.w;
        }
        {
            float4 v = *(const float4*)(W + (size_t)(col0 + lm)*256 + k0 + kq);
            Bs[kq+0][lm] = v.x; Bs[kq+1][lm] = v.y;
            Bs[kq+2][lm] = v.z; Bs[kq+3][lm] = v.w;
        }
        __syncthreads();
        #pragma unroll
        for (int k = 0; k < 16; ++k) {
            float4 a = *(const float4*)(&As[k][tm]);
            float4 b = *(const float4*)(&Bs[k][tn]);
            acc[0][0] += a.x*b.x; acc[0][1] += a.x*b.y; acc[0][2] += a.x*b.z; acc[0][3] += a.x*b.w;
            acc[1][0] += a.y*b.x; acc[1][1] += a.y*b.y; acc[1][2] += a.y*b.z; acc[1][3] += a.y*b.w;
            acc[2][0] += a.z*b.x; acc[2][1] += a.z*b.y; acc[2][2] += a.z*b.z; acc[2][3] += a.z*b.w;
            acc[3][0] += a.w*b.x; acc[3][1] += a.w*b.y; acc[3][2] += a.w*b.z; acc[3][3] += a.w*b.w;
        }
        __syncthreads();
    }

    float4 b4 = *(const float4*)(bias + col0 + tn);
    #pragma unroll
    for (int i = 0; i < 4; ++i) {
        int gr = row0 + tm + i;
        if (gr < M) {
            float4 r;
            r.x = (acc[i][0] + b4.x) * scale;
            r.y = (acc[i][1] + b4.y) * scale;
            r.z = (acc[i][2] + b4.z) * scale;
            r.w = (acc[i][3] + b4.w) * scale;
            *(float4*)(Y + (size_t)gr*256 + col0 + tn) = r;
        }
    }
}

// ---------------------------------------------------------------------------
// K3: vproj via tf32 MMA.  Y[73728,256] = X @ W^T + bias.
// Block tile 128x64, BK=32, 256 threads (8 warps = 4M x 2N), warp tile 32x32.
// A (X) split hi/lo (exact, mask+sub). B (W) = rna-tf32 at staging.
// smem layouts use per-8 k-group permutation [k0,k4,k1,k5,k2,k6,k3,k7] so the
// (k, k+4) fragment register pairs are adjacent -> float2 LDS.
// ---------------------------------------------------------------------------
__global__ void __launch_bounds__(256) vproj_kernel(const float* __restrict__ X,
                                                    const float* __restrict__ W,
                                                    const float* __restrict__ bias,
                                                    float* __restrict__ Y)
{
    __shared__ float xh[128*36];
    __shared__ float xl[128*36];
    __shared__ float ws[64*36];

    int tid  = threadIdx.x;
    int lane = tid & 31, wid = tid >> 5;
    int wm = wid & 3, wn = wid >> 2;
    int row0 = blockIdx.y * 128, col0 = blockIdx.x * 64;
    int r4 = lane >> 2;      // 0..7
    int j  = lane & 3;       // 0..3

    float c[2][4][4] = {};

    for (int k0 = 0; k0 < 256; k0 += 32) {
        __syncthreads();
        // stage X (128 rows x 32 k): 1024 float4 loads, split hi/lo, permuted store
        #pragma unroll
        for (int t = 0; t < 4; ++t) {
            int id  = tid + t*256;
            int row = id >> 3;
            int kq  = (id & 7) * 4;          // 0,4,...,28
            float4 v = *(const float4*)(X + (size_t)(row0+row)*256 + k0 + kq);
            int base = row*36 + (kq>>3)*8 + ((kq&4)>>2);
            float vv[4] = {v.x, v.y, v.z, v.w};
            #pragma unroll
            for (int cc = 0; cc < 4; ++cc) {
                float x  = vv[cc];
                float hi = __uint_as_float(__float_as_uint(x) & 0xffffe000u);
                xh[base + cc*2] = hi;
                xl[base + cc*2] = x - hi;
            }
        }
        // stage W (64 rows x 32 k): rna tf32, permuted store
        #pragma unroll
        for (int t = 0; t < 2; ++t) {
            int id = tid + t*256;
            int nn = id >> 3;
            int kq = (id & 7) * 4;
            float4 v = *(const float4*)(W + (size_t)(col0+nn)*256 + k0 + kq);
            int base = nn*36 + (kq>>3)*8 + ((kq&4)>>2);
            float vv[4] = {v.x, v.y, v.z, v.w};
            #pragma unroll
            for (int cc = 0; cc < 4; ++cc)
                ws[base + cc*2] = cvt_tf32_rna(vv[cc]);
        }
        __syncthreads();

        #pragma unroll
        for (int s = 0; s < 4; ++s) {
            uint32_t b[4][2];
            #pragma unroll
            for (int nt = 0; nt < 4; ++nt) {
                float2 bb = *(const float2*)(ws + (wn*32 + nt*8 + r4)*36 + s*8 + j*2);
                b[nt][0] = f2b(bb.x); b[nt][1] = f2b(bb.y);
            }
            #pragma unroll
            for (int mt = 0; mt < 2; ++mt) {
                int rr = wm*32 + mt*16 + r4;
                float2 h0 = *(const float2*)(xh + rr*36      + s*8 + j*2);
                float2 h1 = *(const float2*)(xh + (rr+8)*36  + s*8 + j*2);
                float2 l0 = *(const float2*)(xl + rr*36      + s*8 + j*2);
                float2 l1 = *(const float2*)(xl + (rr+8)*36  + s*8 + j*2);
                uint32_t ah0=f2b(h0.x), ah1=f2b(h1.x), ah2=f2b(h0.y), ah3=f2b(h1.y);
                uint32_t al0=f2b(l0.x), al1=f2b(l1.x), al2=f2b(l0.y), al3=f2b(l1.y);
                #pragma unroll
                for (int nt = 0; nt < 4; ++nt) {
                    mma_tf32(c[mt][nt], ah0,ah1,ah2,ah3, b[nt][0], b[nt][1]);
                    mma_tf32(c[mt][nt], al0,al1,al2,al3, b[nt][0], b[nt][1]);
                }
            }
        }
    }

    #pragma unroll
    for (int mt = 0; mt < 2; ++mt) {
        int rr = row0 + wm*32 + mt*16 + r4;
        #pragma unroll
        for (int nt = 0; nt < 4; ++nt) {
            int col = col0 + wn*32 + nt*8 + j*2;
            float2 bv = *(const float2*)(bias + col);
            float2 o0 = make_float2(c[mt][nt][0] + bv.x, c[mt][nt][1] + bv.y);
            float2 o1 = make_float2(c[mt][nt][2] + bv.x, c[mt][nt][3] + bv.y);
            *(float2*)(Y + (size_t)rr*256 + col)     = o0;
            *(float2*)(Y + (size_t)(rr+8)*256 + col) = o1;
        }
    }
}

// ---------------------------------------------------------------------------
// K4: scores + softmax (unchanged, exact fp32)
// ---------------------------------------------------------------------------
__global__ void scores_kernel(const float* __restrict__ qp,
                              const float* __restrict__ kp,
                              float* __restrict__ aout)
{
    __shared__ __align__(16) float q_sh[256];
    __shared__ float sc[768];

    int nl = blockIdx.x;
    int n = nl / LL;
    int l = nl - n * LL;
    int tid = threadIdx.x;

    q_sh[tid] = qp[(size_t)nl*256 + tid];
    __syncthreads();

    #pragma unroll
    for (int it = 0; it < 3; ++it) {
        int idx = it*256 + tid;
        int e = idx / 96;
        int x = idx - e * 96;
        const float4* qq = (const float4*)(q_sh + e*32);
        const float4* kk = (const float4*)(kp + ((size_t)(n*96 + x))*256 + e*32);
        float s = 0.f;
        #pragma unroll
        for (int i = 0; i < 8; ++i) {
            float4 q4 = qq[i], k4 = kk[i];
            s += q4.x*k4.x + q4.y*k4.y + q4.z*k4.z + q4.w*k4.w;
        }
        sc[idx] = s;
    }
    __syncthreads();

    int wid = tid >> 5, lane = tid & 31;
    float v0 = sc[wid*96 + lane];
    float v1 = sc[wid*96 + 32 + lane];
    float v2 = sc[wid*96 + 64 + lane];
    float m = fmaxf(v0, fmaxf(v1, v2));
    #pragma unroll
    for (int off = 16; off > 0; off >>= 1)
        m = fmaxf(m, __shfl_xor_sync(0xffffffffu, m, off));
    float e0 = __expf(v0 - m), e1 = __expf(v1 - m), e2 = __expf(v2 - m);
    float s = e0 + e1 + e2;
    #pragma unroll
    for (int off = 16; off > 0; off >>= 1)
        s += __shfl_xor_sync(0xffffffffu, s, off);
    float inv = 1.f / s;
    float* out = aout + (((size_t)(n*8 + wid))*LL + l)*96;
    out[lane]      = e0 * inv;
    out[lane + 32] = e1 * inv;
    out[lane + 64] = e2 * inv;
}

// ---------------------------------------------------------------------------
// K5: attend via tf32 MMA.  Per (n, e, l-tile 64):
//   C[l, d] = sum_{h,w} (acol[l,h]*arow[l,w]) * v[n,h,w,e*32+d]
// 4 warps = 2 M-warps (32 rows) x 2 k-split halves (even/odd h).
// A generated per k-step in regs (fp32 product, exact hi/lo mask split);
// B = v raw fp32 in smem (HW tf32-truncates).  Cross-half smem reduction.
// Dynamic smem: arow_s(perm)[64][96] + acol_s[64][96] + vs[2][32][106] + red[64][32]
// ---------------------------------------------------------------------------
__global__ void __launch_bounds__(128) attend_tf32_kernel(const float* __restrict__ arow,
                                                          const float* __restrict__ acol,
                                                          const float* __restrict__ vp,
                                                          float* __restrict__ attn)
{
    extern __shared__ float sm[];
    float* arow_s = sm;                    // 6144
    float* acol_s = sm + 6144;             // 6144
    float* vs     = sm + 12288;            // 2*32*106 = 6784
    float* red    = sm + 12288 + 6784;     // 64*32 = 2048

    int lt = blockIdx.x, e = blockIdx.y, n = blockIdx.z;
    int tid = threadIdx.x, lane = tid & 31, wid = tid >> 5;
    int wm = wid & 1, half = wid >> 1;
    int l0 = lt * 64;
    int r4 = lane >> 2, j = lane & 3;

    size_t abase = ((size_t)(n*8 + e)) * LL * 96;
    for (int i = tid; i < 64*96; i += 128) {
        int ll = i / 96, x = i - ll*96;
        int lg = l0 + ll;
        float ar = 0.f, ac = 0.f;
        if (lg < LL) {
            ar = arow[abase + (size_t)lg*96 + x];
            ac = acol[abase + (size_t)lg*96 + x];
        }
        int xp = (x & ~7) + ((x & 3) << 1) + ((x >> 2) & 1);
        arow_s[ll*96 + xp] = ar;
        acol_s[i] = ac;
    }

    float c[2][4][4] = {};

    for (int it = 0; it < 48; ++it) {
        __syncthreads();
        // stage 2 h-slabs of v: [d][w-perm], stride 106
        #pragma unroll
        for (int t = 0; t < 12; ++t) {
            int id   = tid + t*128;            // 0..1535
            int slab = id / 768;
            int fid  = id - slab*768;
            int w    = fid >> 3;
            int dq   = (fid & 7) * 4;
            int h    = it*2 + slab;
            float4 v4 = *(const float4*)(vp + (((size_t)(n*HH + h))*WW + w)*EE + e*HDD + dq);
            int wp = (w & ~7) + ((w & 3) << 1) + ((w >> 2) & 1);
            float* dst = vs + slab*3392 + wp;
            dst[(dq+0)*106] = v4.x; dst[(dq+1)*106] = v4.y;
            dst[(dq+2)*106] = v4.z; dst[(dq+3)*106] = v4.w;
        }
        __syncthreads();

        int h = it*2 + half;
        const float* vsl = vs + half*3392;
        float ac_[4];
        ac_[0] = acol_s[(wm*32 +      r4)*96 + h];
        ac_[1] = acol_s[(wm*32 +  8 + r4)*96 + h];
        ac_[2] = acol_s[(wm*32 + 16 + r4)*96 + h];
        ac_[3] = acol_s[(wm*32 + 24 + r4)*96 + h];

        #pragma unroll
        for (int s = 0; s < 12; ++s) {
            uint32_t b[4][2];
            #pragma unroll
            for (int nt = 0; nt < 4; ++nt) {
                float2 bb = *(const float2*)(vsl + (nt*8 + r4)*106 + s*8 + j*2);
                b[nt][0] = f2b(bb.x); b[nt][1] = f2b(bb.y);
            }
            #pragma unroll
            for (int mt = 0; mt < 2; ++mt) {
                int rr = wm*32 + mt*16 + r4;
                float2 a0 = *(const float2*)(arow_s + rr*96     + s*8 + j*2);
                float2 a1 = *(const float2*)(arow_s + (rr+8)*96 + s*8 + j*2);
                float p0 = ac_[mt*2+0] * a0.x;   // (row,   k=j)
                float p1 = ac_[mt*2+1] * a1.x;   // (row+8, k=j)
                float p2 = ac_[mt*2+0] * a0.y;   // (row,   k=j+4)
                float p3 = ac_[mt*2+1] * a1.y;   // (row+8, k=j+4)
                float h0 = __uint_as_float(__float_as_uint(p0) & 0xffffe000u);
                float h1 = __uint_as_float(__float_as_uint(p1) & 0xffffe000u);
                float h2 = __uint_as_float(__float_as_uint(p2) & 0xffffe000u);
                float h3 = __uint_as_float(__float_as_uint(p3) & 0xffffe000u);
                uint32_t ah0=f2b(h0), ah1=f2b(h1), ah2=f2b(h2), ah3=f2b(h3);
                uint32_t al0=f2b(p0-h0), al1=f2b(p1-h1), al2=f2b(p2-h2), al3=f2b(p3-h3);
                #pragma unroll
                for (int nt = 0; nt < 4; ++nt) {
                    mma_tf32(c[mt][nt], ah0,ah1,ah2,ah3, b[nt][0], b[nt][1]);
                    mma_tf32(c[mt][nt], al0,al1,al2,al3, b[nt][0], b[nt][1]);
                }
            }
        }
    }

    __syncthreads();
    if (half == 1) {
        #pragma unroll
        for (int mt = 0; mt < 2; ++mt) {
            int rr = wm*32 + mt*16 + r4;
            #pragma unroll
            for (int nt = 0; nt < 4; ++nt) {
                int col = nt*8 + j*2;
                *(float2*)(red + rr*32 + col)     = make_float2(c[mt][nt][0], c[mt][nt][1]);
                *(float2*)(red + (rr+8)*32 + col) = make_float2(c[mt][nt][2], c[mt][nt][3]);
            }
        }
    }
    __syncthreads();
    if (half == 0) {
        #pragma unroll
        for (int mt = 0; mt < 2; ++mt) {
            int rr = wm*32 + mt*16 + r4;
            int lg0 = l0 + rr, lg1 = l0 + rr + 8;
            #pragma unroll
            for (int nt = 0; nt < 4; ++nt) {
                int col = nt*8 + j*2;
                float2 r0 = *(const float2*)(red + rr*32 + col);
                float2 r1 = *(const float2*)(red + (rr+8)*32 + col);
                if (lg0 < LL)
                    *(float2*)(attn + ((size_t)(lg0*NB + n))*EE + e*HDD + col) =
                        make_float2(c[mt][nt][0] + r0.x, c[mt][nt][1] + r0.y);
                if (lg1 < LL)
                    *(float2*)(attn + ((size_t)(lg1*NB + n))*EE + e*HDD + col) =
                        make_float2(c[mt][nt][2] + r1.x, c[mt][nt][3] + r1.y);
            }
        }
    }
}

// ---------------------------------------------------------------------------
// launch
// ---------------------------------------------------------------------------
static inline float* sym_ptr(const void* sym)
{
    void* p = nullptr;
    cudaGetSymbolAddress(&p, sym);
    return (float*)p;
}

extern "C" void kernel_launch(void* const* d_in, const int* in_sizes, int n_in,
                              void* d_out, int out_size)
{
    const float* query_row = (const float*)d_in[0];
    const float* query_col = (const float*)d_in[1];
    const float* key_row   = (const float*)d_in[2];
    const float* key_col   = (const float*)d_in[3];
    const float* value     = (const float*)d_in[4];
    const float* ipw       = (const float*)d_in[5];
    const float* ipb       = (const float*)d_in[6];
    const float* opw       = (const float*)d_in[7];
    const float* opb       = (const float*)d_in[8];
    float* out = (float*)d_out;

    float* krm  = sym_ptr(g_krm);
    float* kcm  = sym_ptr(g_kcm);
    float* qr   = sym_ptr(g_qr);
    float* qc   = sym_ptr(g_qc);
    float* krp  = sym_ptr(g_krp);
    float* kcp  = sym_ptr(g_kcp);
    float* vp   = sym_ptr(g_vp);
    float* arow = sym_ptr(g_arow);
    float* acol = sym_ptr(g_acol);
    float* attn = sym_ptr(g_attn);

    const float scale = 0.17677669529663687f;   // 32^-0.5
    const int ATT_SMEM = (6144 + 6144 + 6784 + 2048) * 4;   // 84480 B

    cudaFuncSetAttribute(attend_tf32_kernel,
                         cudaFuncAttributeMaxDynamicSharedMemorySize, ATT_SMEM);

    // 1. means
    mean_kernel<<<dim3(96, 2, NB), 256>>>(key_row, key_col, krm, kcm);

    // 2. projections (q/k scalar fp32 exact; v via tf32 MMA)
    gemm_bias_kernel<<<dim3(4, (2400+63)/64), 256>>>(query_row, ipw + 0*EE*EE, ipb + 0*EE, qr, 2400, scale);
    gemm_bias_kernel<<<dim3(4, (2400+63)/64), 256>>>(query_col, ipw + 1*EE*EE, ipb + 1*EE, qc, 2400, scale);
    gemm_bias_kernel<<<dim3(4, 768/64), 256>>>(krm, ipw + 2*EE*EE, ipb + 2*EE, krp, 768, 1.f);
    gemm_bias_kernel<<<dim3(4, 768/64), 256>>>(kcm, ipw + 3*EE*EE, ipb + 3*EE, kcp, 768, 1.f);
    vproj_kernel<<<dim3(4, 576), 256>>>(value, ipw + 4*EE*EE, ipb + 4*EE, vp);

    // 3. scores + softmax
    scores_kernel<<<NB*LL, 256>>>(qr, krp, arow);
    scores_kernel<<<NB*LL, 256>>>(qc, kcp, acol);

    // 4. attend (tf32 MMA)
    attend_tf32_kernel<<<dim3(5, NHD, NB), 128, ATT_SMEM>>>(arow, acol, vp, attn);

    // 5. out projection -> d_out (rows l*8+n), exact fp32
    gemm_bias_kernel<<<dim3(4, (2400+63)/64), 256>>>(attn, opw, opb, out, 2400, 1.f);
}

// round 3
// speedup vs baseline: 2.3665x; 1.1918x over previous
#include <cuda_runtime.h>
#include <cstdint>

// ---------------------------------------------------------------------------
// MultiheadRCDA: row-column decoupled attention.  E=256, NH=8, HD=32,
// N=8, L=300, H=W=96.
//
// Round 3: everything matmul-shaped on tf32 mma.sync.
//  - unified guarded tf32 GEMM (A hi/lo exact split, W rna) for ALL projections
//    + out_proj; the 4 small projections fused into one launch.
//  - attend: generated-A GEMM, single-pass rna-rounded tf32, 256 threads,
//    4-way k-split with smem reduction.
//  - scores row/col fused into one launch.
// ---------------------------------------------------------------------------

#define NB   8
#define LL   300
#define HH   96
#define WW   96
#define EE   256
#define NHD  8
#define HDD  32

__device__ float g_krm[NB*WW*EE];
__device__ float g_kcm[NB*HH*EE];
__device__ float g_qr [NB*LL*EE];
__device__ float g_qc [NB*LL*EE];
__device__ float g_krp[NB*WW*EE];
__device__ float g_kcp[NB*HH*EE];
__device__ float g_vp [NB*HH*WW*EE];       // 75.5 MB
__device__ float g_arow[NB*NHD*LL*WW];
__device__ float g_acol[NB*NHD*LL*HH];
__device__ float g_attn[LL*NB*EE];         // rows ordered l*8+n

__device__ __forceinline__ uint32_t f2b(float x) { return __float_as_uint(x); }

__device__ __forceinline__ void mma_tf32(float* c,
                                         uint32_t a0, uint32_t a1, uint32_t a2, uint32_t a3,
                                         uint32_t b0, uint32_t b1)
{
    asm("mma.sync.aligned.m16n8k8.row.col.f32.tf32.tf32.f32 "
        "{%0,%1,%2,%3}, {%4,%5,%6,%7}, {%8,%9}, {%0,%1,%2,%3};"
        : "+f"(c[0]), "+f"(c[1]), "+f"(c[2]), "+f"(c[3])
        : "r"(a0), "r"(a1), "r"(a2), "r"(a3), "r"(b0), "r"(b1));
}

__device__ __forceinline__ float cvt_tf32_rna(float x)
{
    uint32_t t;
    asm("cvt.rna.tf32.f32 %0, %1;" : "=r"(t) : "f"(x));
    return __uint_as_float(t);
}

// ---------------------------------------------------------------------------
// K1: mean reductions
// ---------------------------------------------------------------------------
__global__ void mean_kernel(const float* __restrict__ key_row,
                            const float* __restrict__ key_col,
                            float* __restrict__ krm,
                            float* __restrict__ kcm)
{
    int idx = blockIdx.x;
    int which = blockIdx.y;
    int n = blockIdx.z;
    int e = threadIdx.x;
    float s = 0.f;
    if (which == 0) {
        const float* p = key_row + ((size_t)n*HH*WW + idx) * EE + e;
        #pragma unroll 8
        for (int h = 0; h < HH; ++h) s += p[(size_t)h*WW*EE];
        krm[(n*WW + idx)*EE + e] = s * (1.f/96.f);
    } else {
        const float* p = key_col + ((size_t)(n*HH + idx)*WW) * EE + e;
        #pragma unroll 8
        for (int w = 0; w < WW; ++w) s += p[(size_t)w*EE];
        kcm[(n*HH + idx)*EE + e] = s * (1.f/96.f);
    }
}

// ---------------------------------------------------------------------------
// Unified tf32 GEMM body: Y[M,256] = (X @ W^T + bias) * scale
// Block tile 128x64, BK=32, 256 threads (4M x 2N warps), warp tile 32x32.
// A (X) hi/lo split at staging (exact); W rna-tf32 at staging.
// Per-8 k-group permutation so (k,k+4) fragment pairs are float2-adjacent.
// ---------------------------------------------------------------------------
__device__ __forceinline__ void gemm_tf32_body(const float* __restrict__ X,
                                               const float* __restrict__ W,
                                               const float* __restrict__ bias,
                                               float* __restrict__ Y,
                                               int M, float scale, int tile_y)
{
    __shared__ float xh[128*36];
    __shared__ float xl[128*36];
    __shared__ float ws[64*36];

    int tid  = threadIdx.x;
    int lane = tid & 31, wid = tid >> 5;
    int wm = wid & 3, wn = wid >> 2;
    int row0 = tile_y * 128, col0 = blockIdx.x * 64;
    int r4 = lane >> 2;
    int j  = lane & 3;

    float c[2][4][4] = {};

    for (int k0 = 0; k0 < 256; k0 += 32) {
        __syncthreads();
        #pragma unroll
        for (int t = 0; t < 4; ++t) {
            int id  = tid + t*256;
            int row = id >> 3;
            int kq  = (id & 7) * 4;
            float4 v = make_float4(0.f,0.f,0.f,0.f);
            if (row0 + row < M)
                v = *(const float4*)(X + (size_t)(row0+row)*256 + k0 + kq);
            int base = row*36 + (kq>>3)*8 + ((kq&4)>>2);
            float vv[4] = {v.x, v.y, v.z, v.w};
            #pragma unroll
            for (int cc = 0; cc < 4; ++cc) {
                float x  = vv[cc];
                float hi = __uint_as_float(__float_as_uint(x) & 0xffffe000u);
                xh[base + cc*2] = hi;
                xl[base + cc*2] = x - hi;
            }
        }
        #pragma unroll
        for (int t = 0; t < 2; ++t) {
            int id = tid + t*256;
            int nn = id >> 3;
            int kq = (id & 7) * 4;
            float4 v = *(const float4*)(W + (size_t)(col0+nn)*256 + k0 + kq);
            int base = nn*36 + (kq>>3)*8 + ((kq&4)>>2);
            float vv[4] = {v.x, v.y, v.z, v.w};
            #pragma unroll
            for (int cc = 0; cc < 4; ++cc)
                ws[base + cc*2] = cvt_tf32_rna(vv[cc]);
        }
        __syncthreads();

        #pragma unroll
        for (int s = 0; s < 4; ++s) {
            uint32_t b[4][2];
            #pragma unroll
            for (int nt = 0; nt < 4; ++nt) {
                float2 bb = *(const float2*)(ws + (wn*32 + nt*8 + r4)*36 + s*8 + j*2);
                b[nt][0] = f2b(bb.x); b[nt][1] = f2b(bb.y);
            }
            #pragma unroll
            for (int mt = 0; mt < 2; ++mt) {
                int rr = wm*32 + mt*16 + r4;
                float2 h0 = *(const float2*)(xh + rr*36      + s*8 + j*2);
                float2 h1 = *(const float2*)(xh + (rr+8)*36  + s*8 + j*2);
                float2 l0 = *(const float2*)(xl + rr*36      + s*8 + j*2);
                float2 l1 = *(const float2*)(xl + (rr+8)*36  + s*8 + j*2);
                uint32_t ah0=f2b(h0.x), ah1=f2b(h1.x), ah2=f2b(h0.y), ah3=f2b(h1.y);
                uint32_t al0=f2b(l0.x), al1=f2b(l1.x), al2=f2b(l0.y), al3=f2b(l1.y);
                #pragma unroll
                for (int nt = 0; nt < 4; ++nt) {
                    mma_tf32(c[mt][nt], ah0,ah1,ah2,ah3, b[nt][0], b[nt][1]);
                    mma_tf32(c[mt][nt], al0,al1,al2,al3, b[nt][0], b[nt][1]);
                }
            }
        }
    }

    #pragma unroll
    for (int mt = 0; mt < 2; ++mt) {
        int rr = row0 + wm*32 + mt*16 + r4;
        #pragma unroll
        for (int nt = 0; nt < 4; ++nt) {
            int col = col0 + wn*32 + nt*8 + j*2;
            float2 bv = *(const float2*)(bias + col);
            if (rr < M)
                *(float2*)(Y + (size_t)rr*256 + col) =
                    make_float2((c[mt][nt][0] + bv.x)*scale, (c[mt][nt][1] + bv.y)*scale);
            if (rr + 8 < M)
                *(float2*)(Y + (size_t)(rr+8)*256 + col) =
                    make_float2((c[mt][nt][2] + bv.x)*scale, (c[mt][nt][3] + bv.y)*scale);
        }
    }
}

__global__ void __launch_bounds__(256) gemm_tf32_kernel(const float* __restrict__ X,
                                                        const float* __restrict__ W,
                                                        const float* __restrict__ bias,
                                                        float* __restrict__ Y,
                                                        int M, float scale)
{
    gemm_tf32_body(X, W, bias, Y, M, scale, blockIdx.y);
}

// 4 small projections fused: tiles_y = [19,19,6,6] -> boundaries 19,38,44,50
__global__ void __launch_bounds__(256) gemm_tf32_multi(const float* __restrict__ x0,
                                                       const float* __restrict__ x1,
                                                       const float* __restrict__ x2,
                                                       const float* __restrict__ x3,
                                                       float* __restrict__ y0,
                                                       float* __restrict__ y1,
                                                       float* __restrict__ y2,
                                                       float* __restrict__ y3,
                                                       const float* __restrict__ ipw,
                                                       const float* __restrict__ ipb,
                                                       float qscale)
{
    int by = blockIdx.y;
    const float* X; float* Y; int M, task, ty; float scale;
    if (by < 19)      { task = 0; ty = by;      X = x0; Y = y0; M = 2400; scale = qscale; }
    else if (by < 38) { task = 1; ty = by - 19; X = x1; Y = y1; M = 2400; scale = qscale; }
    else if (by < 44) { task = 2; ty = by - 38; X = x2; Y = y2; M = 768;  scale = 1.f; }
    else              { task = 3; ty = by - 44; X = x3; Y = y3; M = 768;  scale = 1.f; }
    gemm_tf32_body(X, ipw + (size_t)task*EE*EE, ipb + task*EE, Y, M, scale, ty);
}

// ---------------------------------------------------------------------------
// K4: scores + softmax, row & col fused (blockIdx.y selects)
// ---------------------------------------------------------------------------
__global__ void scores_kernel(const float* __restrict__ qr,
                              const float* __restrict__ krp,
                              float* __restrict__ arow,
                              const float* __restrict__ qc,
                              const float* __restrict__ kcp,
                              float* __restrict__ acol)
{
    __shared__ __align__(16) float q_sh[256];
    __shared__ float sc[768];

    const float* qp  = blockIdx.y ? qc   : qr;
    const float* kp  = blockIdx.y ? kcp  : krp;
    float*       aout= blockIdx.y ? acol : arow;

    int nl = blockIdx.x;
    int n = nl / LL;
    int l = nl - n * LL;
    int tid = threadIdx.x;

    q_sh[tid] = qp[(size_t)nl*256 + tid];
    __syncthreads();

    #pragma unroll
    for (int it = 0; it < 3; ++it) {
        int idx = it*256 + tid;
        int e = idx / 96;
        int x = idx - e * 96;
        const float4* qq = (const float4*)(q_sh + e*32);
        const float4* kk = (const float4*)(kp + ((size_t)(n*96 + x))*256 + e*32);
        float s = 0.f;
        #pragma unroll
        for (int i = 0; i < 8; ++i) {
            float4 q4 = qq[i], k4 = kk[i];
            s += q4.x*k4.x + q4.y*k4.y + q4.z*k4.z + q4.w*k4.w;
        }
        sc[idx] = s;
    }
    __syncthreads();

    int wid = tid >> 5, lane = tid & 31;
    float v0 = sc[wid*96 + lane];
    float v1 = sc[wid*96 + 32 + lane];
    float v2 = sc[wid*96 + 64 + lane];
    float m = fmaxf(v0, fmaxf(v1, v2));
    #pragma unroll
    for (int off = 16; off > 0; off >>= 1)
        m = fmaxf(m, __shfl_xor_sync(0xffffffffu, m, off));
    float e0 = __expf(v0 - m), e1 = __expf(v1 - m), e2 = __expf(v2 - m);
    float s = e0 + e1 + e2;
    #pragma unroll
    for (int off = 16; off > 0; off >>= 1)
        s += __shfl_xor_sync(0xffffffffu, s, off);
    float inv = 1.f / s;
    float* out = aout + (((size_t)(n*8 + wid))*LL + l)*96;
    out[lane]      = e0 * inv;
    out[lane + 32] = e1 * inv;
    out[lane + 64] = e2 * inv;
}

// ---------------------------------------------------------------------------
// K5: attend via tf32 MMA, single-pass rna.  Per (n, e, l-tile 64):
//   C[l, d] = sum_{h,w} (acol[l,h]*arow[l,w]) * v[n,h,w,e*32+d]
// 256 threads = 8 warps = 2 M-halves x 4 k-quarters (h mod 4).
// A product rna-rounded in regs; v rna-rounded at staging.
// smem: arow_s(perm)[64][96], acol_s[64][96], vs[4][32][106] (reused as red).
// ---------------------------------------------------------------------------
__global__ void __launch_bounds__(256) attend_tf32_kernel(const float* __restrict__ arow,
                                                          const float* __restrict__ acol,
                                                          const float* __restrict__ vp,
                                                          float* __restrict__ attn)
{
    extern __shared__ float sm[];
    float* arow_s = sm;                    // 6144
    float* acol_s = sm + 6144;             // 6144
    float* vs     = sm + 12288;            // 4*32*106 = 13568
    float* red    = vs;                    // reused after main loop

    int lt = blockIdx.x, e = blockIdx.y, n = blockIdx.z;
    int tid = threadIdx.x, lane = tid & 31, wid = tid >> 5;
    int wm = wid & 1, kq = wid >> 1;       // M-half, k-quarter
    int l0 = lt * 64;
    int r4 = lane >> 2, j = lane & 3;

    size_t abase = ((size_t)(n*8 + e)) * LL * 96;
    for (int i = tid; i < 64*96; i += 256) {
        int ll = i / 96, x = i - ll*96;
        int lg = l0 + ll;
        float ar = 0.f, ac = 0.f;
        if (lg < LL) {
            ar = arow[abase + (size_t)lg*96 + x];
            ac = acol[abase + (size_t)lg*96 + x];
        }
        int xp = (x & ~7) + ((x & 3) << 1) + ((x >> 2) & 1);
        arow_s[ll*96 + xp] = ar;
        acol_s[i] = ac;
    }

    float c[2][4][4] = {};

    for (int it = 0; it < 24; ++it) {
        __syncthreads();
        // stage 4 h-slabs of v: [d][w-perm], stride 106, rna-rounded
        #pragma unroll
        for (int t = 0; t < 12; ++t) {
            int id   = tid + t*256;            // 0..3071
            int slab = id / 768;
            int fid  = id - slab*768;
            int w    = fid >> 3;
            int dq   = (fid & 7) * 4;
            int h    = it*4 + slab;
            float4 v4 = *(const float4*)(vp + (((size_t)(n*HH + h))*WW + w)*EE + e*HDD + dq);
            int wp = (w & ~7) + ((w & 3) << 1) + ((w >> 2) & 1);
            float* dst = vs + slab*3392 + wp;
            dst[(dq+0)*106] = cvt_tf32_rna(v4.x);
            dst[(dq+1)*106] = cvt_tf32_rna(v4.y);
            dst[(dq+2)*106] = cvt_tf32_rna(v4.z);
            dst[(dq+3)*106] = cvt_tf32_rna(v4.w);
        }
        __syncthreads();

        int h = it*4 + kq;
        const float* vsl = vs + kq*3392;
        float ac_[4];
        ac_[0] = acol_s[(wm*32 +      r4)*96 + h];
        ac_[1] = acol_s[(wm*32 +  8 + r4)*96 + h];
        ac_[2] = acol_s[(wm*32 + 16 + r4)*96 + h];
        ac_[3] = acol_s[(wm*32 + 24 + r4)*96 + h];

        #pragma unroll
        for (int s = 0; s < 12; ++s) {
            uint32_t b[4][2];
            #pragma unroll
            for (int nt = 0; nt < 4; ++nt) {
                float2 bb = *(const float2*)(vsl + (nt*8 + r4)*106 + s*8 + j*2);
                b[nt][0] = f2b(bb.x); b[nt][1] = f2b(bb.y);
            }
            #pragma unroll
            for (int mt = 0; mt < 2; ++mt) {
                int rr = wm*32 + mt*16 + r4;
                float2 a0 = *(const float2*)(arow_s + rr*96     + s*8 + j*2);
                float2 a1 = *(const float2*)(arow_s + (rr+8)*96 + s*8 + j*2);
                uint32_t a_0 = f2b(cvt_tf32_rna(ac_[mt*2+0] * a0.x));
                uint32_t a_1 = f2b(cvt_tf32_rna(ac_[mt*2+1] * a1.x));
                uint32_t a_2 = f2b(cvt_tf32_rna(ac_[mt*2+0] * a0.y));
                uint32_t a_3 = f2b(cvt_tf32_rna(ac_[mt*2+1] * a1.y));
                #pragma unroll
                for (int nt = 0; nt < 4; ++nt)
                    mma_tf32(c[mt][nt], a_0, a_1, a_2, a_3, b[nt][0], b[nt][1]);
            }
        }
    }

    __syncthreads();
    if (kq != 0) {
        float* dst = red + (kq-1)*2048;
        #pragma unroll
        for (int mt = 0; mt < 2; ++mt) {
            int rr = wm*32 + mt*16 + r4;
            #pragma unroll
            for (int nt = 0; nt < 4; ++nt) {
                int col = nt*8 + j*2;
                *(float2*)(dst + rr*32 + col)     = make_float2(c[mt][nt][0], c[mt][nt][1]);
                *(float2*)(dst + (rr+8)*32 + col) = make_float2(c[mt][nt][2], c[mt][nt][3]);
            }
        }
    }
    __syncthreads();
    if (kq == 0) {
        #pragma unroll
        for (int mt = 0; mt < 2; ++mt) {
            int rr = wm*32 + mt*16 + r4;
            int lg0 = l0 + rr, lg1 = l0 + rr + 8;
            #pragma unroll
            for (int nt = 0; nt < 4; ++nt) {
                int col = nt*8 + j*2;
                float s0 = c[mt][nt][0], s1 = c[mt][nt][1];
                float s2 = c[mt][nt][2], s3 = c[mt][nt][3];
                #pragma unroll
                for (int q = 0; q < 3; ++q) {
                    const float* src = red + q*2048;
                    float2 r0 = *(const float2*)(src + rr*32 + col);
                    float2 r1 = *(const float2*)(src + (rr+8)*32 + col);
                    s0 += r0.x; s1 += r0.y; s2 += r1.x; s3 += r1.y;
                }
                if (lg0 < LL)
                    *(float2*)(attn + ((size_t)(lg0*NB + n))*EE + e*HDD + col) = make_float2(s0, s1);
                if (lg1 < LL)
                    *(float2*)(attn + ((size_t)(lg1*NB + n))*EE + e*HDD + col) = make_float2(s2, s3);
            }
        }
    }
}

// ---------------------------------------------------------------------------
// launch
// ---------------------------------------------------------------------------
static inline float* sym_ptr(const void* sym)
{
    void* p = nullptr;
    cudaGetSymbolAddress(&p, sym);
    return (float*)p;
}

extern "C" void kernel_launch(void* const* d_in, const int* in_sizes, int n_in,
                              void* d_out, int out_size)
{
    const float* query_row = (const float*)d_in[0];
    const float* query_col = (const float*)d_in[1];
    const float* key_row   = (const float*)d_in[2];
    const float* key_col   = (const float*)d_in[3];
    const float* value     = (const float*)d_in[4];
    const float* ipw       = (const float*)d_in[5];
    const float* ipb       = (const float*)d_in[6];
    const float* opw       = (const float*)d_in[7];
    const float* opb       = (const float*)d_in[8];
    float* out = (float*)d_out;

    float* krm  = sym_ptr(g_krm);
    float* kcm  = sym_ptr(g_kcm);
    float* qr   = sym_ptr(g_qr);
    float* qc   = sym_ptr(g_qc);
    float* krp  = sym_ptr(g_krp);
    float* kcp  = sym_ptr(g_kcp);
    float* vp   = sym_ptr(g_vp);
    float* arow = sym_ptr(g_arow);
    float* acol = sym_ptr(g_acol);
    float* attn = sym_ptr(g_attn);

    const float scale = 0.17677669529663687f;   // 32^-0.5
    const int ATT_SMEM = (6144 + 6144 + 13568) * 4;   // 103424 B

    cudaFuncSetAttribute(attend_tf32_kernel,
                         cudaFuncAttributeMaxDynamicSharedMemorySize, ATT_SMEM);

    // 1. means
    mean_kernel<<<dim3(96, 2, NB), 256>>>(key_row, key_col, krm, kcm);

    // 2a. v projection (independent of mean) — biggest GEMM
    gemm_tf32_kernel<<<dim3(4, 576), 256>>>(value, ipw + 4*EE*EE, ipb + 4*EE, vp, 73728, 1.f);

    // 2b. q_row/q_col/k_row/k_col projections fused in one launch
    gemm_tf32_multi<<<dim3(4, 50), 256>>>(query_row, query_col, krm, kcm,
                                          qr, qc, krp, kcp, ipw, ipb, scale);

    // 3. scores + softmax (row & col fused)
    scores_kernel<<<dim3(NB*LL, 2), 256>>>(qr, krp, arow, qc, kcp, acol);

    // 4. attend (tf32 MMA, single pass)
    attend_tf32_kernel<<<dim3(5, NHD, NB), 256, ATT_SMEM>>>(arow, acol, vp, attn);

    // 5. out projection -> d_out (rows l*8+n)
    gemm_tf32_kernel<<<dim3(4, 19), 256>>>(attn, opw, opb, out, 2400, 1.f);
}

// round 4
// speedup vs baseline: 2.9782x; 1.2585x over previous
#include <cuda_runtime.h>
#include <cstdint>

// ---------------------------------------------------------------------------
// MultiheadRCDA: row-column decoupled attention.  E=256, NH=8, HD=32,
// N=8, L=300, H=W=96.
//
// Round 4:
//  - scores: block per (n,which,head), K-slice in smem, q via shfl  (reuse fix)
//  - vproj: single-pass rna tf32 (attend re-rounds v anyway), output
//    pre-rounded to tf32; attend staging cvt dropped.
//  - q/k/out projections keep exact hi/lo A-split tf32.
// ---------------------------------------------------------------------------

#define NB   8
#define LL   300
#define HH   96
#define WW   96
#define EE   256
#define NHD  8
#define HDD  32

__device__ float g_krm[NB*WW*EE];
__device__ float g_kcm[NB*HH*EE];
__device__ float g_qr [NB*LL*EE];
__device__ float g_qc [NB*LL*EE];
__device__ float g_krp[NB*WW*EE];
__device__ float g_kcp[NB*HH*EE];
__device__ float g_vp [NB*HH*WW*EE];       // 75.5 MB
__device__ float g_arow[NB*NHD*LL*WW];
__device__ float g_acol[NB*NHD*LL*HH];
__device__ float g_attn[LL*NB*EE];         // rows ordered l*8+n

__device__ __forceinline__ uint32_t f2b(float x) { return __float_as_uint(x); }

__device__ __forceinline__ void mma_tf32(float* c,
                                         uint32_t a0, uint32_t a1, uint32_t a2, uint32_t a3,
                                         uint32_t b0, uint32_t b1)
{
    asm("mma.sync.aligned.m16n8k8.row.col.f32.tf32.tf32.f32 "
        "{%0,%1,%2,%3}, {%4,%5,%6,%7}, {%8,%9}, {%0,%1,%2,%3};"
        : "+f"(c[0]), "+f"(c[1]), "+f"(c[2]), "+f"(c[3])
        : "r"(a0), "r"(a1), "r"(a2), "r"(a3), "r"(b0), "r"(b1));
}

__device__ __forceinline__ float cvt_tf32_rna(float x)
{
    uint32_t t;
    asm("cvt.rna.tf32.f32 %0, %1;" : "=r"(t) : "f"(x));
    return __uint_as_float(t);
}

// ---------------------------------------------------------------------------
// K1: mean reductions
// ---------------------------------------------------------------------------
__global__ void mean_kernel(const float* __restrict__ key_row,
                            const float* __restrict__ key_col,
                            float* __restrict__ krm,
                            float* __restrict__ kcm)
{
    int idx = blockIdx.x;
    int which = blockIdx.y;
    int n = blockIdx.z;
    int e = threadIdx.x;
    float s = 0.f;
    if (which == 0) {
        const float* p = key_row + ((size_t)n*HH*WW + idx) * EE + e;
        #pragma unroll 8
        for (int h = 0; h < HH; ++h) s += p[(size_t)h*WW*EE];
        krm[(n*WW + idx)*EE + e] = s * (1.f/96.f);
    } else {
        const float* p = key_col + ((size_t)(n*HH + idx)*WW) * EE + e;
        #pragma unroll 8
        for (int w = 0; w < WW; ++w) s += p[(size_t)w*EE];
        kcm[(n*HH + idx)*EE + e] = s * (1.f/96.f);
    }
}

// ---------------------------------------------------------------------------
// Unified tf32 GEMM body: Y[M,256] = (X @ W^T + bias) * scale
// Block tile 128x64, BK=32, 256 threads (4M x 2N warps), warp tile 32x32.
// SPLIT=1: A hi/lo exact split (2 MMAs).  SPLIT=0: A rna single-pass (1 MMA).
// ROUND=1: round the stored output to tf32 (for v feeding attend).
// ---------------------------------------------------------------------------
template<int SPLIT, int ROUND>
__device__ __forceinline__ void gemm_tf32_body(const float* __restrict__ X,
                                               const float* __restrict__ W,
                                               const float* __restrict__ bias,
                                               float* __restrict__ Y,
                                               int M, float scale, int tile_y)
{
    __shared__ float xh[128*36];
    __shared__ float xl[SPLIT ? 128*36 : 1];
    __shared__ float ws[64*36];

    int tid  = threadIdx.x;
    int lane = tid & 31, wid = tid >> 5;
    int wm = wid & 3, wn = wid >> 2;
    int row0 = tile_y * 128, col0 = blockIdx.x * 64;
    int r4 = lane >> 2;
    int j  = lane & 3;

    float c[2][4][4] = {};

    for (int k0 = 0; k0 < 256; k0 += 32) {
        __syncthreads();
        #pragma unroll
        for (int t = 0; t < 4; ++t) {
            int id  = tid + t*256;
            int row = id >> 3;
            int kq  = (id & 7) * 4;
            float4 v = make_float4(0.f,0.f,0.f,0.f);
            if (row0 + row < M)
                v = *(const float4*)(X + (size_t)(row0+row)*256 + k0 + kq);
            int base = row*36 + (kq>>3)*8 + ((kq&4)>>2);
            float vv[4] = {v.x, v.y, v.z, v.w};
            #pragma unroll
            for (int cc = 0; cc < 4; ++cc) {
                float x  = vv[cc];
                if (SPLIT) {
                    float hi = __uint_as_float(__float_as_uint(x) & 0xffffe000u);
                    xh[base + cc*2] = hi;
                    xl[base + cc*2] = x - hi;
                } else {
                    xh[base + cc*2] = cvt_tf32_rna(x);
                }
            }
        }
        #pragma unroll
        for (int t = 0; t < 2; ++t) {
            int id = tid + t*256;
            int nn = id >> 3;
            int kq = (id & 7) * 4;
            float4 v = *(const float4*)(W + (size_t)(col0+nn)*256 + k0 + kq);
            int base = nn*36 + (kq>>3)*8 + ((kq&4)>>2);
            float vv[4] = {v.x, v.y, v.z, v.w};
            #pragma unroll
            for (int cc = 0; cc < 4; ++cc)
                ws[base + cc*2] = cvt_tf32_rna(vv[cc]);
        }
        __syncthreads();

        #pragma unroll
        for (int s = 0; s < 4; ++s) {
            uint32_t b[4][2];
            #pragma unroll
            for (int nt = 0; nt < 4; ++nt) {
                float2 bb = *(const float2*)(ws + (wn*32 + nt*8 + r4)*36 + s*8 + j*2);
                b[nt][0] = f2b(bb.x); b[nt][1] = f2b(bb.y);
            }
            #pragma unroll
            for (int mt = 0; mt < 2; ++mt) {
                int rr = wm*32 + mt*16 + r4;
                float2 h0 = *(const float2*)(xh + rr*36      + s*8 + j*2);
                float2 h1 = *(const float2*)(xh + (rr+8)*36  + s*8 + j*2);
                uint32_t ah0=f2b(h0.x), ah1=f2b(h1.x), ah2=f2b(h0.y), ah3=f2b(h1.y);
                #pragma unroll
                for (int nt = 0; nt < 4; ++nt)
                    mma_tf32(c[mt][nt], ah0,ah1,ah2,ah3, b[nt][0], b[nt][1]);
                if (SPLIT) {
                    float2 l0 = *(const float2*)(xl + rr*36      + s*8 + j*2);
                    float2 l1 = *(const float2*)(xl + (rr+8)*36  + s*8 + j*2);
                    uint32_t al0=f2b(l0.x), al1=f2b(l1.x), al2=f2b(l0.y), al3=f2b(l1.y);
                    #pragma unroll
                    for (int nt = 0; nt < 4; ++nt)
                        mma_tf32(c[mt][nt], al0,al1,al2,al3, b[nt][0], b[nt][1]);
                }
            }
        }
    }

    #pragma unroll
    for (int mt = 0; mt < 2; ++mt) {
        int rr = row0 + wm*32 + mt*16 + r4;
        #pragma unroll
        for (int nt = 0; nt < 4; ++nt) {
            int col = col0 + wn*32 + nt*8 + j*2;
            float2 bv = *(const float2*)(bias + col);
            float o0 = (c[mt][nt][0] + bv.x)*scale, o1 = (c[mt][nt][1] + bv.y)*scale;
            float o2 = (c[mt][nt][2] + bv.x)*scale, o3 = (c[mt][nt][3] + bv.y)*scale;
            if (ROUND) {
                o0 = cvt_tf32_rna(o0); o1 = cvt_tf32_rna(o1);
                o2 = cvt_tf32_rna(o2); o3 = cvt_tf32_rna(o3);
            }
            if (rr < M)
                *(float2*)(Y + (size_t)rr*256 + col) = make_float2(o0, o1);
            if (rr + 8 < M)
                *(float2*)(Y + (size_t)(rr+8)*256 + col) = make_float2(o2, o3);
        }
    }
}

__global__ void __launch_bounds__(256) gemm_tf32_kernel(const float* __restrict__ X,
                                                        const float* __restrict__ W,
                                                        const float* __restrict__ bias,
                                                        float* __restrict__ Y,
                                                        int M, float scale)
{
    gemm_tf32_body<1,0>(X, W, bias, Y, M, scale, blockIdx.y);
}

__global__ void __launch_bounds__(256) vproj_kernel(const float* __restrict__ X,
                                                    const float* __restrict__ W,
                                                    const float* __restrict__ bias,
                                                    float* __restrict__ Y)
{
    gemm_tf32_body<0,1>(X, W, bias, Y, 73728, 1.f, blockIdx.y);
}

// 4 small projections fused: tiles_y = [19,19,6,6] -> boundaries 19,38,44,50
__global__ void __launch_bounds__(256) gemm_tf32_multi(const float* __restrict__ x0,
                                                       const float* __restrict__ x1,
                                                       const float* __restrict__ x2,
                                                       const float* __restrict__ x3,
                                                       float* __restrict__ y0,
                                                       float* __restrict__ y1,
                                                       float* __restrict__ y2,
                                                       float* __restrict__ y3,
                                                       const float* __restrict__ ipw,
                                                       const float* __restrict__ ipb,
                                                       float qscale)
{
    int by = blockIdx.y;
    const float* X; float* Y; int M, task, ty; float scale;
    if (by < 19)      { task = 0; ty = by;      X = x0; Y = y0; M = 2400; scale = qscale; }
    else if (by < 38) { task = 1; ty = by - 19; X = x1; Y = y1; M = 2400; scale = qscale; }
    else if (by < 44) { task = 2; ty = by - 38; X = x2; Y = y2; M = 768;  scale = 1.f; }
    else              { task = 3; ty = by - 44; X = x3; Y = y3; M = 768;  scale = 1.f; }
    gemm_tf32_body<1,0>(X, ipw + (size_t)task*EE*EE, ipb + task*EE, Y, M, scale, ty);
}

// ---------------------------------------------------------------------------
// K4: scores + softmax.  Block per (head, which, n): K-slice (96x32) in smem,
// reused across all 300 query rows; q row broadcast via shfl.
// ---------------------------------------------------------------------------
__global__ void __launch_bounds__(256) scores_kernel(const float* __restrict__ qr,
                                                     const float* __restrict__ krp,
                                                     float* __restrict__ arow,
                                                     const float* __restrict__ qc,
                                                     const float* __restrict__ kcp,
                                                     float* __restrict__ acol)
{
    __shared__ float k_s[32][97];      // [d][x], padded

    int head = blockIdx.x, which = blockIdx.y, n = blockIdx.z;
    const float* qp   = which ? qc   : qr;
    const float* kp   = which ? kcp  : krp;
    float*       aout = which ? acol : arow;

    int tid = threadIdx.x;
    // stage K: 96 x  x 32 d  (3 passes of 32x x 8 float4)
    #pragma unroll
    for (int p = 0; p < 3; ++p) {
        int x  = p*32 + (tid >> 3);
        int d4 = (tid & 7) * 4;
        float4 v = *(const float4*)(kp + ((size_t)(n*96 + x))*256 + head*32 + d4);
        k_s[d4+0][x] = v.x; k_s[d4+1][x] = v.y;
        k_s[d4+2][x] = v.z; k_s[d4+3][x] = v.w;
    }
    __syncthreads();

    int wid = tid >> 5, lane = tid & 31;
    for (int l = wid; l < LL; l += 8) {
        float qv = qp[((size_t)(n*LL + l))*256 + head*32 + lane];
        float s0 = 0.f, s1 = 0.f, s2 = 0.f;
        #pragma unroll
        for (int d = 0; d < 32; ++d) {
            float qd = __shfl_sync(0xffffffffu, qv, d);
            s0 += qd * k_s[d][lane];
            s1 += qd * k_s[d][lane + 32];
            s2 += qd * k_s[d][lane + 64];
        }
        float m = fmaxf(s0, fmaxf(s1, s2));
        #pragma unroll
        for (int off = 16; off > 0; off >>= 1)
            m = fmaxf(m, __shfl_xor_sync(0xffffffffu, m, off));
        float e0 = __expf(s0 - m), e1 = __expf(s1 - m), e2 = __expf(s2 - m);
        float s = e0 + e1 + e2;
        #pragma unroll
        for (int off = 16; off > 0; off >>= 1)
            s += __shfl_xor_sync(0xffffffffu, s, off);
        float inv = 1.f / s;
        float* out = aout + (((size_t)(n*8 + head))*LL + l)*96;
        out[lane]      = e0 * inv;
        out[lane + 32] = e1 * inv;
        out[lane + 64] = e2 * inv;
    }
}

// ---------------------------------------------------------------------------
// K5: attend via tf32 MMA, single-pass rna.  Per (n, e, l-tile 64):
//   C[l, d] = sum_{h,w} (acol[l,h]*arow[l,w]) * v[n,h,w,e*32+d]
// 256 threads = 8 warps = 2 M-halves x 4 k-quarters.  v is pre-rounded tf32.
// ---------------------------------------------------------------------------
__global__ void __launch_bounds__(256) attend_tf32_kernel(const float* __restrict__ arow,
                                                          const float* __restrict__ acol,
                                                          const float* __restrict__ vp,
                                                          float* __restrict__ attn)
{
    extern __shared__ float sm[];
    float* arow_s = sm;                    // 6144
    float* acol_s = sm + 6144;             // 6144
    float* vs     = sm + 12288;            // 4*32*106 = 13568
    float* red    = vs;                    // reused after main loop

    int lt = blockIdx.x, e = blockIdx.y, n = blockIdx.z;
    int tid = threadIdx.x, lane = tid & 31, wid = tid >> 5;
    int wm = wid & 1, kq = wid >> 1;
    int l0 = lt * 64;
    int r4 = lane >> 2, j = lane & 3;

    size_t abase = ((size_t)(n*8 + e)) * LL * 96;
    for (int i = tid; i < 64*96; i += 256) {
        int ll = i / 96, x = i - ll*96;
        int lg = l0 + ll;
        float ar = 0.f, ac = 0.f;
        if (lg < LL) {
            ar = arow[abase + (size_t)lg*96 + x];
            ac = acol[abase + (size_t)lg*96 + x];
        }
        int xp = (x & ~7) + ((x & 3) << 1) + ((x >> 2) & 1);
        arow_s[ll*96 + xp] = ar;
        acol_s[i] = ac;
    }

    float c[2][4][4] = {};

    for (int it = 0; it < 24; ++it) {
        __syncthreads();
        #pragma unroll
        for (int t = 0; t < 12; ++t) {
            int id   = tid + t*256;
            int slab = id / 768;
            int fid  = id - slab*768;
            int w    = fid >> 3;
            int dq   = (fid & 7) * 4;
            int h    = it*4 + slab;
            float4 v4 = *(const float4*)(vp + (((size_t)(n*HH + h))*WW + w)*EE + e*HDD + dq);
            int wp = (w & ~7) + ((w & 3) << 1) + ((w >> 2) & 1);
            float* dst = vs + slab*3392 + wp;
            dst[(dq+0)*106] = v4.x;
            dst[(dq+1)*106] = v4.y;
            dst[(dq+2)*106] = v4.z;
            dst[(dq+3)*106] = v4.w;
        }
        __syncthreads();

        int h = it*4 + kq;
        const float* vsl = vs + kq*3392;
        float ac_[4];
        ac_[0] = acol_s[(wm*32 +      r4)*96 + h];
        ac_[1] = acol_s[(wm*32 +  8 + r4)*96 + h];
        ac_[2] = acol_s[(wm*32 + 16 + r4)*96 + h];
        ac_[3] = acol_s[(wm*32 + 24 + r4)*96 + h];

        #pragma unroll
        for (int s = 0; s < 12; ++s) {
            uint32_t b[4][2];
            #pragma unroll
            for (int nt = 0; nt < 4; ++nt) {
                float2 bb = *(const float2*)(vsl + (nt*8 + r4)*106 + s*8 + j*2);
                b[nt][0] = f2b(bb.x); b[nt][1] = f2b(bb.y);
            }
            #pragma unroll
            for (int mt = 0; mt < 2; ++mt) {
                int rr = wm*32 + mt*16 + r4;
                float2 a0 = *(const float2*)(arow_s + rr*96     + s*8 + j*2);
                float2 a1 = *(const float2*)(arow_s + (rr+8)*96 + s*8 + j*2);
                uint32_t a_0 = f2b(cvt_tf32_rna(ac_[mt*2+0] * a0.x));
                uint32_t a_1 = f2b(cvt_tf32_rna(ac_[mt*2+1] * a1.x));
                uint32_t a_2 = f2b(cvt_tf32_rna(ac_[mt*2+0] * a0.y));
                uint32_t a_3 = f2b(cvt_tf32_rna(ac_[mt*2+1] * a1.y));
                #pragma unroll
                for (int nt = 0; nt < 4; ++nt)
                    mma_tf32(c[mt][nt], a_0, a_1, a_2, a_3, b[nt][0], b[nt][1]);
            }
        }
    }

    __syncthreads();
    if (kq != 0) {
        float* dst = red + (kq-1)*2048;
        #pragma unroll
        for (int mt = 0; mt < 2; ++mt) {
            int rr = wm*32 + mt*16 + r4;
            #pragma unroll
            for (int nt = 0; nt < 4; ++nt) {
                int col = nt*8 + j*2;
                *(float2*)(dst + rr*32 + col)     = make_float2(c[mt][nt][0], c[mt][nt][1]);
                *(float2*)(dst + (rr+8)*32 + col) = make_float2(c[mt][nt][2], c[mt][nt][3]);
            }
        }
    }
    __syncthreads();
    if (kq == 0) {
        #pragma unroll
        for (int mt = 0; mt < 2; ++mt) {
            int rr = wm*32 + mt*16 + r4;
            int lg0 = l0 + rr, lg1 = l0 + rr + 8;
            #pragma unroll
            for (int nt = 0; nt < 4; ++nt) {
                int col = nt*8 + j*2;
                float s0 = c[mt][nt][0], s1 = c[mt][nt][1];
                float s2 = c[mt][nt][2], s3 = c[mt][nt][3];
                #pragma unroll
                for (int q = 0; q < 3; ++q) {
                    const float* src = red + q*2048;
                    float2 r0 = *(const float2*)(src + rr*32 + col);
                    float2 r1 = *(const float2*)(src + (rr+8)*32 + col);
                    s0 += r0.x; s1 += r0.y; s2 += r1.x; s3 += r1.y;
                }
                if (lg0 < LL)
                    *(float2*)(attn + ((size_t)(lg0*NB + n))*EE + e*HDD + col) = make_float2(s0, s1);
                if (lg1 < LL)
                    *(float2*)(attn + ((size_t)(lg1*NB + n))*EE + e*HDD + col) = make_float2(s2, s3);
            }
        }
    }
}

// ---------------------------------------------------------------------------
// launch
// ---------------------------------------------------------------------------
static inline float* sym_ptr(const void* sym)
{
    void* p = nullptr;
    cudaGetSymbolAddress(&p, sym);
    return (float*)p;
}

extern "C" void kernel_launch(void* const* d_in, const int* in_sizes, int n_in,
                              void* d_out, int out_size)
{
    const float* query_row = (const float*)d_in[0];
    const float* query_col = (const float*)d_in[1];
    const float* key_row   = (const float*)d_in[2];
    const float* key_col   = (const float*)d_in[3];
    const float* value     = (const float*)d_in[4];
    const float* ipw       = (const float*)d_in[5];
    const float* ipb       = (const float*)d_in[6];
    const float* opw       = (const float*)d_in[7];
    const float* opb       = (const float*)d_in[8];
    float* out = (float*)d_out;

    float* krm  = sym_ptr(g_krm);
    float* kcm  = sym_ptr(g_kcm);
    float* qr   = sym_ptr(g_qr);
    float* qc   = sym_ptr(g_qc);
    float* krp  = sym_ptr(g_krp);
    float* kcp  = sym_ptr(g_kcp);
    float* vp   = sym_ptr(g_vp);
    float* arow = sym_ptr(g_arow);
    float* acol = sym_ptr(g_acol);
    float* attn = sym_ptr(g_attn);

    const float scale = 0.17677669529663687f;   // 32^-0.5
    const int ATT_SMEM = (6144 + 6144 + 13568) * 4;   // 103424 B

    cudaFuncSetAttribute(attend_tf32_kernel,
                         cudaFuncAttributeMaxDynamicSharedMemorySize, ATT_SMEM);

    // 1. means
    mean_kernel<<<dim3(96, 2, NB), 256>>>(key_row, key_col, krm, kcm);

    // 2a. v projection (single-pass rna, output pre-rounded to tf32)
    vproj_kernel<<<dim3(4, 576), 256>>>(value, ipw + 4*EE*EE, ipb + 4*EE, vp);

    // 2b. q_row/q_col/k_row/k_col projections fused (exact hi/lo)
    gemm_tf32_multi<<<dim3(4, 50), 256>>>(query_row, query_col, krm, kcm,
                                          qr, qc, krp, kcp, ipw, ipb, scale);

    // 3. scores + softmax (K-slice resident in smem)
    scores_kernel<<<dim3(NHD, 2, NB), 256>>>(qr, krp, arow, qc, kcp, acol);

    // 4. attend (tf32 MMA, single pass)
    attend_tf32_kernel<<<dim3(5, NHD, NB), 256, ATT_SMEM>>>(arow, acol, vp, attn);

    // 5. out projection -> d_out (rows l*8+n), exact hi/lo
    gemm_tf32_kernel<<<dim3(4, 19), 256>>>(attn, opw, opb, out, 2400, 1.f);
}

// round 5
// speedup vs baseline: 4.0982x; 1.3760x over previous
#include <cuda_runtime.h>
#include <cstdint>

// ---------------------------------------------------------------------------
// MultiheadRCDA: row-column decoupled attention.  E=256, NH=8, HD=32,
// N=8, L=300, H=W=96.
//
// Round 5:
//  - scores: L tiled 5x -> 640 blocks (was 128, occ 12%)
//  - vproj writes transposed vpt[n][h][e][d][w]; output pre-rounded tf32
//  - attend: cp.async double-buffered straight-copy v staging, 4M x 2K warps,
//    conflict-free smem strides (100 / 104), 1-partial reduction
// ---------------------------------------------------------------------------

#define NB   8
#define LL   300
#define HH   96
#define WW   96
#define EE   256
#define NHD  8
#define HDD  32

__device__ float g_krm[NB*WW*EE];
__device__ float g_kcm[NB*HH*EE];
__device__ float g_qr [NB*LL*EE];
__device__ float g_qc [NB*LL*EE];
__device__ float g_krp[NB*WW*EE];
__device__ float g_kcp[NB*HH*EE];
__device__ float g_vpt[NB*HH*NHD*HDD*WW];   // [n][h][e][d][w]  75.5 MB
__device__ float g_arow[NB*NHD*LL*WW];
__device__ float g_acol[NB*NHD*LL*HH];
__device__ float g_attn[LL*NB*EE];          // rows ordered l*8+n

__device__ __forceinline__ uint32_t f2b(float x) { return __float_as_uint(x); }

__device__ __forceinline__ void mma_tf32(float* c,
                                         uint32_t a0, uint32_t a1, uint32_t a2, uint32_t a3,
                                         uint32_t b0, uint32_t b1)
{
    asm("mma.sync.aligned.m16n8k8.row.col.f32.tf32.tf32.f32 "
        "{%0,%1,%2,%3}, {%4,%5,%6,%7}, {%8,%9}, {%0,%1,%2,%3};"
        : "+f"(c[0]), "+f"(c[1]), "+f"(c[2]), "+f"(c[3])
        : "r"(a0), "r"(a1), "r"(a2), "r"(a3), "r"(b0), "r"(b1));
}

__device__ __forceinline__ float cvt_tf32_rna(float x)
{
    uint32_t t;
    asm("cvt.rna.tf32.f32 %0, %1;" : "=r"(t) : "f"(x));
    return __uint_as_float(t);
}

__device__ __forceinline__ void cp_async16(uint32_t dst_smem, const void* src)
{
    asm volatile("cp.async.cg.shared.global [%0], [%1], 16;" :: "r"(dst_smem), "l"(src));
}

// ---------------------------------------------------------------------------
// K1: mean reductions
// ---------------------------------------------------------------------------
__global__ void mean_kernel(const float* __restrict__ key_row,
                            const float* __restrict__ key_col,
                            float* __restrict__ krm,
                            float* __restrict__ kcm)
{
    int idx = blockIdx.x;
    int which = blockIdx.y;
    int n = blockIdx.z;
    int e = threadIdx.x;
    float s = 0.f;
    if (which == 0) {
        const float* p = key_row + ((size_t)n*HH*WW + idx) * EE + e;
        #pragma unroll 8
        for (int h = 0; h < HH; ++h) s += p[(size_t)h*WW*EE];
        krm[(n*WW + idx)*EE + e] = s * (1.f/96.f);
    } else {
        const float* p = key_col + ((size_t)(n*HH + idx)*WW) * EE + e;
        #pragma unroll 8
        for (int w = 0; w < WW; ++w) s += p[(size_t)w*EE];
        kcm[(n*HH + idx)*EE + e] = s * (1.f/96.f);
    }
}

// ---------------------------------------------------------------------------
// Unified tf32 GEMM body: Y = (X @ W^T + bias) * scale
// SPLIT: A hi/lo exact (2 MMA) vs rna single-pass.  ROUND: round output.
// VPT: store transposed into vpt[n][h][e][d][w]  (rows are (n,h,w), cols (e,d))
// ---------------------------------------------------------------------------
template<int SPLIT, int ROUND, int VPT>
__device__ __forceinline__ void gemm_tf32_body(const float* __restrict__ X,
                                               const float* __restrict__ W,
                                               const float* __restrict__ bias,
                                               float* __restrict__ Y,
                                               int M, float scale, int tile_y)
{
    __shared__ float xh[128*36];
    __shared__ float xl[SPLIT ? 128*36 : 1];
    __shared__ float ws[64*36];

    int tid  = threadIdx.x;
    int lane = tid & 31, wid = tid >> 5;
    int wm = wid & 3, wn = wid >> 2;
    int row0 = tile_y * 128, col0 = blockIdx.x * 64;
    int r4 = lane >> 2;
    int j  = lane & 3;

    float c[2][4][4] = {};

    for (int k0 = 0; k0 < 256; k0 += 32) {
        __syncthreads();
        #pragma unroll
        for (int t = 0; t < 4; ++t) {
            int id  = tid + t*256;
            int row = id >> 3;
            int kq  = (id & 7) * 4;
            float4 v = make_float4(0.f,0.f,0.f,0.f);
            if (row0 + row < M)
                v = *(const float4*)(X + (size_t)(row0+row)*256 + k0 + kq);
            int base = row*36 + (kq>>3)*8 + ((kq&4)>>2);
            float vv[4] = {v.x, v.y, v.z, v.w};
            #pragma unroll
            for (int cc = 0; cc < 4; ++cc) {
                float x  = vv[cc];
                if (SPLIT) {
                    float hi = __uint_as_float(__float_as_uint(x) & 0xffffe000u);
                    xh[base + cc*2] = hi;
                    xl[base + cc*2] = x - hi;
                } else {
                    xh[base + cc*2] = cvt_tf32_rna(x);
                }
            }
        }
        #pragma unroll
        for (int t = 0; t < 2; ++t) {
            int id = tid + t*256;
            int nn = id >> 3;
            int kq = (id & 7) * 4;
            float4 v = *(const float4*)(W + (size_t)(col0+nn)*256 + k0 + kq);
            int base = nn*36 + (kq>>3)*8 + ((kq&4)>>2);
            float vv[4] = {v.x, v.y, v.z, v.w};
            #pragma unroll
            for (int cc = 0; cc < 4; ++cc)
                ws[base + cc*2] = cvt_tf32_rna(vv[cc]);
        }
        __syncthreads();

        #pragma unroll
        for (int s = 0; s < 4; ++s) {
            uint32_t b[4][2];
            #pragma unroll
            for (int nt = 0; nt < 4; ++nt) {
                float2 bb = *(const float2*)(ws + (wn*32 + nt*8 + r4)*36 + s*8 + j*2);
                b[nt][0] = f2b(bb.x); b[nt][1] = f2b(bb.y);
            }
            #pragma unroll
            for (int mt = 0; mt < 2; ++mt) {
                int rr = wm*32 + mt*16 + r4;
                float2 h0 = *(const float2*)(xh + rr*36      + s*8 + j*2);
                float2 h1 = *(const float2*)(xh + (rr+8)*36  + s*8 + j*2);
                uint32_t ah0=f2b(h0.x), ah1=f2b(h1.x), ah2=f2b(h0.y), ah3=f2b(h1.y);
                #pragma unroll
                for (int nt = 0; nt < 4; ++nt)
                    mma_tf32(c[mt][nt], ah0,ah1,ah2,ah3, b[nt][0], b[nt][1]);
                if (SPLIT) {
                    float2 l0 = *(const float2*)(xl + rr*36      + s*8 + j*2);
                    float2 l1 = *(const float2*)(xl + (rr+8)*36  + s*8 + j*2);
                    uint32_t al0=f2b(l0.x), al1=f2b(l1.x), al2=f2b(l0.y), al3=f2b(l1.y);
                    #pragma unroll
                    for (int nt = 0; nt < 4; ++nt)
                        mma_tf32(c[mt][nt], al0,al1,al2,al3, b[nt][0], b[nt][1]);
                }
            }
        }
    }

    #pragma unroll
    for (int mt = 0; mt < 2; ++mt) {
        int rr = row0 + wm*32 + mt*16 + r4;
        int n0, h0r, w0r, n1, h1r, w1r;
        if (VPT) {
            n0 = rr / 9216; int rem0 = rr - n0*9216; h0r = rem0 / 96; w0r = rem0 - h0r*96;
            int rb = rr + 8;
            n1 = rb / 9216; int rem1 = rb - n1*9216; h1r = rem1 / 96; w1r = rem1 - h1r*96;
        }
        #pragma unroll
        for (int nt = 0; nt < 4; ++nt) {
            int col = col0 + wn*32 + nt*8 + j*2;
            float2 bv = *(const float2*)(bias + col);
            float o0 = (c[mt][nt][0] + bv.x)*scale, o1 = (c[mt][nt][1] + bv.y)*scale;
            float o2 = (c[mt][nt][2] + bv.x)*scale, o3 = (c[mt][nt][3] + bv.y)*scale;
            if (ROUND) {
                o0 = cvt_tf32_rna(o0); o1 = cvt_tf32_rna(o1);
                o2 = cvt_tf32_rna(o2); o3 = cvt_tf32_rna(o3);
            }
            if (VPT) {
                int e = col >> 5, d = col & 31;
                size_t b0 = (((size_t)(n0*96 + h0r)*8 + e)*32 + d)*96 + w0r;
                size_t b1 = (((size_t)(n1*96 + h1r)*8 + e)*32 + d)*96 + w1r;
                Y[b0] = o0; Y[b0 + 96] = o1;
                Y[b1] = o2; Y[b1 + 96] = o3;
            } else {
                if (rr < M)
                    *(float2*)(Y + (size_t)rr*256 + col) = make_float2(o0, o1);
                if (rr + 8 < M)
                    *(float2*)(Y + (size_t)(rr+8)*256 + col) = make_float2(o2, o3);
            }
        }
    }
}

__global__ void __launch_bounds__(256) gemm_tf32_kernel(const float* __restrict__ X,
                                                        const float* __restrict__ W,
                                                        const float* __restrict__ bias,
                                                        float* __restrict__ Y,
                                                        int M, float scale)
{
    gemm_tf32_body<1,0,0>(X, W, bias, Y, M, scale, blockIdx.y);
}

__global__ void __launch_bounds__(256) vproj_kernel(const float* __restrict__ X,
                                                    const float* __restrict__ W,
                                                    const float* __restrict__ bias,
                                                    float* __restrict__ Y)
{
    gemm_tf32_body<0,1,1>(X, W, bias, Y, 73728, 1.f, blockIdx.y);
}

// 4 small projections fused: tiles_y = [19,19,6,6]
__global__ void __launch_bounds__(256) gemm_tf32_multi(const float* __restrict__ x0,
                                                       const float* __restrict__ x1,
                                                       const float* __restrict__ x2,
                                                       const float* __restrict__ x3,
                                                       float* __restrict__ y0,
                                                       float* __restrict__ y1,
                                                       float* __restrict__ y2,
                                                       float* __restrict__ y3,
                                                       const float* __restrict__ ipw,
                                                       const float* __restrict__ ipb,
                                                       float qscale)
{
    int by = blockIdx.y;
    const float* X; float* Y; int M, task, ty; float scale;
    if (by < 19)      { task = 0; ty = by;      X = x0; Y = y0; M = 2400; scale = qscale; }
    else if (by < 38) { task = 1; ty = by - 19; X = x1; Y = y1; M = 2400; scale = qscale; }
    else if (by < 44) { task = 2; ty = by - 38; X = x2; Y = y2; M = 768;  scale = 1.f; }
    else              { task = 3; ty = by - 44; X = x3; Y = y3; M = 768;  scale = 1.f; }
    gemm_tf32_body<1,0,0>(X, ipw + (size_t)task*EE*EE, ipb + task*EE, Y, M, scale, ty);
}

// ---------------------------------------------------------------------------
// K4: scores + softmax.  Block per (head, which, n x ltile); K-slice in smem.
// ---------------------------------------------------------------------------
#define SC_LT 5
__global__ void __launch_bounds__(256) scores_kernel(const float* __restrict__ qr,
                                                     const float* __restrict__ krp,
                                                     float* __restrict__ arow,
                                                     const float* __restrict__ qc,
                                                     const float* __restrict__ kcp,
                                                     float* __restrict__ acol)
{
    __shared__ float k_s[32][97];

    int head = blockIdx.x, which = blockIdx.y;
    int n = blockIdx.z / SC_LT, lt = blockIdx.z - n*SC_LT;
    const float* qp   = which ? qc   : qr;
    const float* kp   = which ? kcp  : krp;
    float*       aout = which ? acol : arow;

    int tid = threadIdx.x;
    #pragma unroll
    for (int p = 0; p < 3; ++p) {
        int x  = p*32 + (tid >> 3);
        int d4 = (tid & 7) * 4;
        float4 v = *(const float4*)(kp + ((size_t)(n*96 + x))*256 + head*32 + d4);
        k_s[d4+0][x] = v.x; k_s[d4+1][x] = v.y;
        k_s[d4+2][x] = v.z; k_s[d4+3][x] = v.w;
    }
    __syncthreads();

    int wid = tid >> 5, lane = tid & 31;
    int lend = lt*60 + 60; if (lend > LL) lend = LL;
    for (int l = lt*60 + wid; l < lend; l += 8) {
        float qv = qp[((size_t)(n*LL + l))*256 + head*32 + lane];
        float s0 = 0.f, s1 = 0.f, s2 = 0.f;
        #pragma unroll
        for (int d = 0; d < 32; ++d) {
            float qd = __shfl_sync(0xffffffffu, qv, d);
            s0 += qd * k_s[d][lane];
            s1 += qd * k_s[d][lane + 32];
            s2 += qd * k_s[d][lane + 64];
        }
        float m = fmaxf(s0, fmaxf(s1, s2));
        #pragma unroll
        for (int off = 16; off > 0; off >>= 1)
            m = fmaxf(m, __shfl_xor_sync(0xffffffffu, m, off));
        float e0 = __expf(s0 - m), e1 = __expf(s1 - m), e2 = __expf(s2 - m);
        float s = e0 + e1 + e2;
        #pragma unroll
        for (int off = 16; off > 0; off >>= 1)
            s += __shfl_xor_sync(0xffffffffu, s, off);
        float inv = 1.f / s;
        float* out = aout + (((size_t)(n*8 + head))*LL + l)*96;
        out[lane]      = e0 * inv;
        out[lane + 32] = e1 * inv;
        out[lane + 64] = e2 * inv;
    }
}

// ---------------------------------------------------------------------------
// K5: attend.  Per (n, e, l-tile 64):
//   C[l, d] = sum_{h,w} (acol[l,h]*arow[l,w]) * v[n,h,w,e*32+d]
// 8 warps = 4 M-tiles (m16) x 2-way h-split.  v from vpt via cp.async into a
// 2-stage double buffer ([d][w] stride 100, conflict-free).  arow permuted
// stride 104 (conflict-free LDS.64).  1-partial k-reduction overlaid on vs.
//
// smem (floats): vs 4*3200=12800 | arow 64*104=6656 | acol 64*97=6208
//   red (overlays vs, stride 40): 64*40=2560.   total 25664 fl = 100.3 KB
// ---------------------------------------------------------------------------
#define VS_STR  100
#define AR_STR  104
#define AC_STR  97
#define SLAB_F  3200          // 32*VS_STR

__global__ void __launch_bounds__(256) attend_tf32_kernel(const float* __restrict__ arow,
                                                          const float* __restrict__ acol,
                                                          const float* __restrict__ vpt,
                                                          float* __restrict__ attn)
{
    extern __shared__ float sm[];
    float* vs     = sm;                       // 12800
    float* arow_s = sm + 12800;               // 6656
    float* acol_s = sm + 12800 + 6656;        // 6208
    float* red    = vs;                       // reused after main loop

    int lt = blockIdx.x, e = blockIdx.y, n = blockIdx.z;
    int tid = threadIdx.x, lane = tid & 31, wid = tid >> 5;
    int wm = wid & 3, kh = wid >> 2;
    int l0 = lt * 64;
    int r4 = lane >> 2, j = lane & 3;

    uint32_t vs_u = (uint32_t)__cvta_generic_to_shared(vs);
    const float* vbase = vpt + ((size_t)(n*96)*8 + e) * 3072;

    // stage attention maps
    size_t abase = ((size_t)(n*8 + e)) * LL * 96;
    for (int i = tid; i < 64*96; i += 256) {
        int ll = i / 96, x = i - ll*96;
        int lg = l0 + ll;
        float ar = 0.f, ac = 0.f;
        if (lg < LL) {
            ar = arow[abase + (size_t)lg*96 + x];
            ac = acol[abase + (size_t)lg*96 + x];
        }
        int xp = (x & ~7) + ((x & 3) << 1) + ((x >> 2) & 1);
        arow_s[ll*AR_STR + xp] = ar;
        acol_s[ll*AC_STR + x]  = ac;
    }

    // prefetch stage 0 (h=0,1)
    #pragma unroll
    for (int t = 0; t < 6; ++t) {
        int cch  = tid + t*256;
        int slab = cch / 768;
        int r    = cch - slab*768;
        int dd   = r / 24;
        int ck   = r - dd*24;
        cp_async16(vs_u + (slab*SLAB_F + dd*VS_STR + ck*4)*4,
                   vbase + (size_t)slab*24576 + dd*96 + ck*4);
    }
    asm volatile("cp.async.commit_group;");

    float c[4][4] = {};

    for (int it = 0; it < 48; ++it) {
        int buf = it & 1;
        if (it + 1 < 48) {
            int nbuf = buf ^ 1;
            #pragma unroll
            for (int t = 0; t < 6; ++t) {
                int cch  = tid + t*256;
                int slab = cch / 768;
                int r    = cch - slab*768;
                int dd   = r / 24;
                int ck   = r - dd*24;
                int h    = (it+1)*2 + slab;
                cp_async16(vs_u + (nbuf*2*SLAB_F + slab*SLAB_F + dd*VS_STR + ck*4)*4,
                           vbase + (size_t)h*24576 + dd*96 + ck*4);
            }
            asm volatile("cp.async.commit_group;");
            asm volatile("cp.async.wait_group 1;");
        } else {
            asm volatile("cp.async.wait_group 0;");
        }
        __syncthreads();

        int h = it*2 + kh;
        const float* vsl = vs + buf*2*SLAB_F + kh*SLAB_F;
        float ac0 = acol_s[(wm*16 +     r4)*AC_STR + h];
        float ac1 = acol_s[(wm*16 + 8 + r4)*AC_STR + h];

        #pragma unroll
        for (int s = 0; s < 12; ++s) {
            uint32_t b[4][2];
            #pragma unroll
            for (int nt = 0; nt < 4; ++nt) {
                b[nt][0] = f2b(vsl[(nt*8 + r4)*VS_STR + s*8 + j]);
                b[nt][1] = f2b(vsl[(nt*8 + r4)*VS_STR + s*8 + j + 4]);
            }
            float2 a0 = *(const float2*)(arow_s + (wm*16 +     r4)*AR_STR + s*8 + j*2);
            float2 a1 = *(const float2*)(arow_s + (wm*16 + 8 + r4)*AR_STR + s*8 + j*2);
            uint32_t a_0 = f2b(cvt_tf32_rna(ac0 * a0.x));
            uint32_t a_1 = f2b(cvt_tf32_rna(ac1 * a1.x));
            uint32_t a_2 = f2b(cvt_tf32_rna(ac0 * a0.y));
            uint32_t a_3 = f2b(cvt_tf32_rna(ac1 * a1.y));
            #pragma unroll
            for (int nt = 0; nt < 4; ++nt)
                mma_tf32(c[nt], a_0, a_1, a_2, a_3, b[nt][0], b[nt][1]);
        }
        __syncthreads();
    }

    // k-reduction: kh=1 writes partials, kh=0 adds + stores
    if (kh == 1) {
        int rr = wm*16 + r4;
        #pragma unroll
        for (int nt = 0; nt < 4; ++nt) {
            int col = nt*8 + j*2;
            *(float2*)(red + rr*40 + col)     = make_float2(c[nt][0], c[nt][1]);
            *(float2*)(red + (rr+8)*40 + col) = make_float2(c[nt][2], c[nt][3]);
        }
    }
    __syncthreads();
    if (kh == 0) {
        int rr = wm*16 + r4;
        int lg0 = l0 + rr, lg1 = l0 + rr + 8;
        #pragma unroll
        for (int nt = 0; nt < 4; ++nt) {
            int col = nt*8 + j*2;
            float2 r0 = *(const float2*)(red + rr*40 + col);
            float2 r1 = *(const float2*)(red + (rr+8)*40 + col);
            if (lg0 < LL)
                *(float2*)(attn + ((size_t)(lg0*NB + n))*EE + e*HDD + col) =
                    make_float2(c[nt][0] + r0.x, c[nt][1] + r0.y);
            if (lg1 < LL)
                *(float2*)(attn + ((size_t)(lg1*NB + n))*EE + e*HDD + col) =
                    make_float2(c[nt][2] + r1.x, c[nt][3] + r1.y);
        }
    }
}

// ---------------------------------------------------------------------------
// launch
// ---------------------------------------------------------------------------
static inline float* sym_ptr(const void* sym)
{
    void* p = nullptr;
    cudaGetSymbolAddress(&p, sym);
    return (float*)p;
}

extern "C" void kernel_launch(void* const* d_in, const int* in_sizes, int n_in,
                              void* d_out, int out_size)
{
    const float* query_row = (const float*)d_in[0];
    const float* query_col = (const float*)d_in[1];
    const float* key_row   = (const float*)d_in[2];
    const float* key_col   = (const float*)d_in[3];
    const float* value     = (const float*)d_in[4];
    const float* ipw       = (const float*)d_in[5];
    const float* ipb       = (const float*)d_in[6];
    const float* opw       = (const float*)d_in[7];
    const float* opb       = (const float*)d_in[8];
    float* out = (float*)d_out;

    float* krm  = sym_ptr(g_krm);
    float* kcm  = sym_ptr(g_kcm);
    float* qr   = sym_ptr(g_qr);
    float* qc   = sym_ptr(g_qc);
    float* krp  = sym_ptr(g_krp);
    float* kcp  = sym_ptr(g_kcp);
    float* vpt  = sym_ptr(g_vpt);
    float* arow = sym_ptr(g_arow);
    float* acol = sym_ptr(g_acol);
    float* attn = sym_ptr(g_attn);

    const float scale = 0.17677669529663687f;   // 32^-0.5
    const int ATT_SMEM = (12800 + 6656 + 6208) * 4;   // 102656 B

    cudaFuncSetAttribute(attend_tf32_kernel,
                         cudaFuncAttributeMaxDynamicSharedMemorySize, ATT_SMEM);

    // 1. means
    mean_kernel<<<dim3(96, 2, NB), 256>>>(key_row, key_col, krm, kcm);

    // 2a. v projection -> transposed vpt, pre-rounded tf32
    vproj_kernel<<<dim3(4, 576), 256>>>(value, ipw + 4*EE*EE, ipb + 4*EE, vpt);

    // 2b. q_row/q_col/k_row/k_col projections fused (exact hi/lo)
    gemm_tf32_multi<<<dim3(4, 50), 256>>>(query_row, query_col, krm, kcm,
                                          qr, qc, krp, kcp, ipw, ipb, scale);

    // 3. scores + softmax (L tiled 5x)
    scores_kernel<<<dim3(NHD, 2, NB*SC_LT), 256>>>(qr, krp, arow, qc, kcp, acol);

    // 4. attend (cp.async pipelined tf32 MMA)
    attend_tf32_kernel<<<dim3(5, NHD, NB), 256, ATT_SMEM>>>(arow, acol, vpt, attn);

    // 5. out projection -> d_out (rows l*8+n), exact hi/lo
    gemm_tf32_kernel<<<dim3(4, 19), 256>>>(attn, opw, opb, out, 2400, 1.f);
}

// round 6
// speedup vs baseline: 4.6175x; 1.1267x over previous
#include <cuda_runtime.h>
#include <cstdint>

// ---------------------------------------------------------------------------
// MultiheadRCDA: row-column decoupled attention.  E=256, NH=8, HD=32,
// N=8, L=300, H=W=96.
//
// Round 6:
//  - unified GEMM body: register-prefetch software pipeline (LDG for next
//    k-chunk overlaps MMA compute), templated BN
//  - vproj: BN=128 tile (halved X staging traffic per MMA)
//  - scores: 2 query rows per sweep (halved LDS/FMA ratio)
// ---------------------------------------------------------------------------

#define NB   8
#define LL   300
#define HH   96
#define WW   96
#define EE   256
#define NHD  8
#define HDD  32

__device__ float g_krm[NB*WW*EE];
__device__ float g_kcm[NB*HH*EE];
__device__ float g_qr [NB*LL*EE];
__device__ float g_qc [NB*LL*EE];
__device__ float g_krp[NB*WW*EE];
__device__ float g_kcp[NB*HH*EE];
__device__ float g_vpt[NB*HH*NHD*HDD*WW];   // [n][h][e][d][w]  75.5 MB
__device__ float g_arow[NB*NHD*LL*WW];
__device__ float g_acol[NB*NHD*LL*HH];
__device__ float g_attn[LL*NB*EE];          // rows ordered l*8+n

__device__ __forceinline__ uint32_t f2b(float x) { return __float_as_uint(x); }

__device__ __forceinline__ void mma_tf32(float* c,
                                         uint32_t a0, uint32_t a1, uint32_t a2, uint32_t a3,
                                         uint32_t b0, uint32_t b1)
{
    asm("mma.sync.aligned.m16n8k8.row.col.f32.tf32.tf32.f32 "
        "{%0,%1,%2,%3}, {%4,%5,%6,%7}, {%8,%9}, {%0,%1,%2,%3};"
        : "+f"(c[0]), "+f"(c[1]), "+f"(c[2]), "+f"(c[3])
        : "r"(a0), "r"(a1), "r"(a2), "r"(a3), "r"(b0), "r"(b1));
}

__device__ __forceinline__ float cvt_tf32_rna(float x)
{
    uint32_t t;
    asm("cvt.rna.tf32.f32 %0, %1;" : "=r"(t) : "f"(x));
    return __uint_as_float(t);
}

__device__ __forceinline__ void cp_async16(uint32_t dst_smem, const void* src)
{
    asm volatile("cp.async.cg.shared.global [%0], [%1], 16;" :: "r"(dst_smem), "l"(src));
}

// ---------------------------------------------------------------------------
// K1: mean reductions
// ---------------------------------------------------------------------------
__global__ void mean_kernel(const float* __restrict__ key_row,
                            const float* __restrict__ key_col,
                            float* __restrict__ krm,
                            float* __restrict__ kcm)
{
    int idx = blockIdx.x;
    int which = blockIdx.y;
    int n = blockIdx.z;
    int e = threadIdx.x;
    float s = 0.f;
    if (which == 0) {
        const float* p = key_row + ((size_t)n*HH*WW + idx) * EE + e;
        #pragma unroll 8
        for (int h = 0; h < HH; ++h) s += p[(size_t)h*WW*EE];
        krm[(n*WW + idx)*EE + e] = s * (1.f/96.f);
    } else {
        const float* p = key_col + ((size_t)(n*HH + idx)*WW) * EE + e;
        #pragma unroll 8
        for (int w = 0; w < WW; ++w) s += p[(size_t)w*EE];
        kcm[(n*HH + idx)*EE + e] = s * (1.f/96.f);
    }
}

// ---------------------------------------------------------------------------
// Unified tf32 GEMM body: Y = (X @ W^T + bias) * scale, K=256 fixed.
// 256 threads, 8 warps = 4M x 2N.  Block tile 128 x BN.  BK=32.
// Register-prefetch pipeline: LDG for k0+32 issued before computing k0.
// SPLIT: A hi/lo exact (2 MMA).  ROUND: tf32-round output.  VPT: transposed
// store into vpt[n][h][e][d][w].
// ---------------------------------------------------------------------------
template<int SPLIT, int ROUND, int VPT, int BN>
__device__ __forceinline__ void gemm_tf32_body(const float* __restrict__ X,
                                               const float* __restrict__ W,
                                               const float* __restrict__ bias,
                                               float* __restrict__ Y,
                                               int M, float scale, int tile_y)
{
    constexpr int WT = BN/32;     // W float4 loads per thread
    constexpr int NT = BN/16;     // n-tiles (n8) per warp

    __shared__ float xh[128*36];
    __shared__ float xl[SPLIT ? 128*36 : 1];
    __shared__ float ws[BN*36];

    int tid  = threadIdx.x;
    int lane = tid & 31, wid = tid >> 5;
    int wm = wid & 3, wn = wid >> 2;
    int row0 = tile_y * 128, col0 = blockIdx.x * BN;
    int r4 = lane >> 2;
    int j  = lane & 3;

    int lrow = tid >> 3;              // 0..31
    int kq4  = (tid & 7) * 4;         // 0,4,...,28
    int sb   = (kq4>>3)*8 + ((kq4&4)>>2);

    float4 xr[4], wr[WT];

    // prefetch k0 = 0
    #pragma unroll
    for (int t = 0; t < 4; ++t) {
        int row = row0 + lrow + t*32;
        xr[t] = make_float4(0.f,0.f,0.f,0.f);
        if (row < M) xr[t] = *(const float4*)(X + (size_t)row*256 + kq4);
    }
    #pragma unroll
    for (int t = 0; t < WT; ++t)
        wr[t] = *(const float4*)(W + (size_t)(col0 + lrow + t*32)*256 + kq4);

    float c[2][NT][4] = {};

    for (int k0 = 0; k0 < 256; k0 += 32) {
        __syncthreads();    // previous compute done; smem reusable
        #pragma unroll
        for (int t = 0; t < 4; ++t) {
            int base = (lrow + t*32)*36 + sb;
            float vv[4] = {xr[t].x, xr[t].y, xr[t].z, xr[t].w};
            #pragma unroll
            for (int cc = 0; cc < 4; ++cc) {
                float x = vv[cc];
                if (SPLIT) {
                    float hi = __uint_as_float(__float_as_uint(x) & 0xffffe000u);
                    xh[base + cc*2] = hi;
                    xl[base + cc*2] = x - hi;
                } else {
                    xh[base + cc*2] = cvt_tf32_rna(x);
                }
            }
        }
        #pragma unroll
        for (int t = 0; t < WT; ++t) {
            int base = (lrow + t*32)*36 + sb;
            float vv[4] = {wr[t].x, wr[t].y, wr[t].z, wr[t].w};
            #pragma unroll
            for (int cc = 0; cc < 4; ++cc)
                ws[base + cc*2] = cvt_tf32_rna(vv[cc]);
        }
        __syncthreads();    // stores visible

        if (k0 < 224) {     // prefetch next chunk; LDG latency overlaps MMAs
            int kn = k0 + 32;
            #pragma unroll
            for (int t = 0; t < 4; ++t) {
                int row = row0 + lrow + t*32;
                xr[t] = make_float4(0.f,0.f,0.f,0.f);
                if (row < M) xr[t] = *(const float4*)(X + (size_t)row*256 + kn + kq4);
            }
            #pragma unroll
            for (int t = 0; t < WT; ++t)
                wr[t] = *(const float4*)(W + (size_t)(col0 + lrow + t*32)*256 + kn + kq4);
        }

        #pragma unroll
        for (int s = 0; s < 4; ++s) {
            uint32_t b[NT][2];
            #pragma unroll
            for (int nt = 0; nt < NT; ++nt) {
                float2 bb = *(const float2*)(ws + (wn*(BN/2) + nt*8 + r4)*36 + s*8 + j*2);
                b[nt][0] = f2b(bb.x); b[nt][1] = f2b(bb.y);
            }
            #pragma unroll
            for (int mt = 0; mt < 2; ++mt) {
                int rr = wm*32 + mt*16 + r4;
                float2 h0 = *(const float2*)(xh + rr*36      + s*8 + j*2);
                float2 h1 = *(const float2*)(xh + (rr+8)*36  + s*8 + j*2);
                uint32_t ah0=f2b(h0.x), ah1=f2b(h1.x), ah2=f2b(h0.y), ah3=f2b(h1.y);
                #pragma unroll
                for (int nt = 0; nt < NT; ++nt)
                    mma_tf32(c[mt][nt], ah0,ah1,ah2,ah3, b[nt][0], b[nt][1]);
                if (SPLIT) {
                    float2 l0 = *(const float2*)(xl + rr*36      + s*8 + j*2);
                    float2 l1 = *(const float2*)(xl + (rr+8)*36  + s*8 + j*2);
                    uint32_t al0=f2b(l0.x), al1=f2b(l1.x), al2=f2b(l0.y), al3=f2b(l1.y);
                    #pragma unroll
                    for (int nt = 0; nt < NT; ++nt)
                        mma_tf32(c[mt][nt], al0,al1,al2,al3, b[nt][0], b[nt][1]);
                }
            }
        }
    }

    #pragma unroll
    for (int mt = 0; mt < 2; ++mt) {
        int rr = row0 + wm*32 + mt*16 + r4;
        int n0, h0r, w0r, n1, h1r, w1r;
        if (VPT) {
            n0 = rr / 9216; int rem0 = rr - n0*9216; h0r = rem0 / 96; w0r = rem0 - h0r*96;
            int rb = rr + 8;
            n1 = rb / 9216; int rem1 = rb - n1*9216; h1r = rem1 / 96; w1r = rem1 - h1r*96;
        }
        #pragma unroll
        for (int nt = 0; nt < NT; ++nt) {
            int col = col0 + wn*(BN/2) + nt*8 + j*2;
            float2 bv = *(const float2*)(bias + col);
            float o0 = (c[mt][nt][0] + bv.x)*scale, o1 = (c[mt][nt][1] + bv.y)*scale;
            float o2 = (c[mt][nt][2] + bv.x)*scale, o3 = (c[mt][nt][3] + bv.y)*scale;
            if (ROUND) {
                o0 = cvt_tf32_rna(o0); o1 = cvt_tf32_rna(o1);
                o2 = cvt_tf32_rna(o2); o3 = cvt_tf32_rna(o3);
            }
            if (VPT) {
                int e = col >> 5, d = col & 31;
                size_t b0 = (((size_t)(n0*96 + h0r)*8 + e)*32 + d)*96 + w0r;
                size_t b1 = (((size_t)(n1*96 + h1r)*8 + e)*32 + d)*96 + w1r;
                Y[b0] = o0; Y[b0 + 96] = o1;
                Y[b1] = o2; Y[b1 + 96] = o3;
            } else {
                if (rr < M)
                    *(float2*)(Y + (size_t)rr*256 + col) = make_float2(o0, o1);
                if (rr + 8 < M)
                    *(float2*)(Y + (size_t)(rr+8)*256 + col) = make_float2(o2, o3);
            }
        }
    }
}

__global__ void __launch_bounds__(256) gemm_tf32_kernel(const float* __restrict__ X,
                                                        const float* __restrict__ W,
                                                        const float* __restrict__ bias,
                                                        float* __restrict__ Y,
                                                        int M, float scale)
{
    gemm_tf32_body<1,0,0,64>(X, W, bias, Y, M, scale, blockIdx.y);
}

__global__ void __launch_bounds__(256) vproj_kernel(const float* __restrict__ X,
                                                    const float* __restrict__ W,
                                                    const float* __restrict__ bias,
                                                    float* __restrict__ Y)
{
    gemm_tf32_body<0,1,1,128>(X, W, bias, Y, 73728, 1.f, blockIdx.y);
}

// 4 small projections fused: tiles_y = [19,19,6,6]
__global__ void __launch_bounds__(256) gemm_tf32_multi(const float* __restrict__ x0,
                                                       const float* __restrict__ x1,
                                                       const float* __restrict__ x2,
                                                       const float* __restrict__ x3,
                                                       float* __restrict__ y0,
                                                       float* __restrict__ y1,
                                                       float* __restrict__ y2,
                                                       float* __restrict__ y3,
                                                       const float* __restrict__ ipw,
                                                       const float* __restrict__ ipb,
                                                       float qscale)
{
    int by = blockIdx.y;
    const float* X; float* Y; int M, task, ty; float scale;
    if (by < 19)      { task = 0; ty = by;      X = x0; Y = y0; M = 2400; scale = qscale; }
    else if (by < 38) { task = 1; ty = by - 19; X = x1; Y = y1; M = 2400; scale = qscale; }
    else if (by < 44) { task = 2; ty = by - 38; X = x2; Y = y2; M = 768;  scale = 1.f; }
    else              { task = 3; ty = by - 44; X = x3; Y = y3; M = 768;  scale = 1.f; }
    gemm_tf32_body<1,0,0,64>(X, ipw + (size_t)task*EE*EE, ipb + task*EE, Y, M, scale, ty);
}

// ---------------------------------------------------------------------------
// K4: scores + softmax.  Block per (head, which, n x ltile); K-slice in smem.
// Each warp owns an 8-row strip, processes 2 query rows per sweep.
// ---------------------------------------------------------------------------
#define SC_LT 5
__global__ void __launch_bounds__(256) scores_kernel(const float* __restrict__ qr,
                                                     const float* __restrict__ krp,
                                                     float* __restrict__ arow,
                                                     const float* __restrict__ qc,
                                                     const float* __restrict__ kcp,
                                                     float* __restrict__ acol)
{
    __shared__ float k_s[32][97];

    int head = blockIdx.x, which = blockIdx.y;
    int n = blockIdx.z / SC_LT, lt = blockIdx.z - n*SC_LT;
    const float* qp   = which ? qc   : qr;
    const float* kp   = which ? kcp  : krp;
    float*       aout = which ? acol : arow;

    int tid = threadIdx.x;
    #pragma unroll
    for (int p = 0; p < 3; ++p) {
        int x  = p*32 + (tid >> 3);
        int d4 = (tid & 7) * 4;
        float4 v = *(const float4*)(kp + ((size_t)(n*96 + x))*256 + head*32 + d4);
        k_s[d4+0][x] = v.x; k_s[d4+1][x] = v.y;
        k_s[d4+2][x] = v.z; k_s[d4+3][x] = v.w;
    }
    __syncthreads();

    int wid = tid >> 5, lane = tid & 31;
    int lend = lt*60 + 60;               // 5*60 == 300 exactly
    int lbeg = lt*60 + wid*8;
    #pragma unroll
    for (int sIt = 0; sIt < 8; sIt += 2) {
        int l0 = lbeg + sIt, l1 = l0 + 1;
        bool v0 = (l0 < lend), v1 = (l1 < lend);
        float q0 = v0 ? qp[((size_t)(n*LL + l0))*256 + head*32 + lane] : 0.f;
        float q1 = v1 ? qp[((size_t)(n*LL + l1))*256 + head*32 + lane] : 0.f;
        float s00=0.f,s01=0.f,s02=0.f, s10=0.f,s11=0.f,s12=0.f;
        #pragma unroll
        for (int d = 0; d < 32; ++d) {
            float qd0 = __shfl_sync(0xffffffffu, q0, d);
            float qd1 = __shfl_sync(0xffffffffu, q1, d);
            float k0 = k_s[d][lane], k1 = k_s[d][lane+32], k2 = k_s[d][lane+64];
            s00 += qd0*k0; s01 += qd0*k1; s02 += qd0*k2;
            s10 += qd1*k0; s11 += qd1*k1; s12 += qd1*k2;
        }
        // softmax l0
        float m0 = fmaxf(s00, fmaxf(s01, s02));
        float m1 = fmaxf(s10, fmaxf(s11, s12));
        #pragma unroll
        for (int off = 16; off > 0; off >>= 1) {
            m0 = fmaxf(m0, __shfl_xor_sync(0xffffffffu, m0, off));
            m1 = fmaxf(m1, __shfl_xor_sync(0xffffffffu, m1, off));
        }
        float e00 = __expf(s00-m0), e01 = __expf(s01-m0), e02 = __expf(s02-m0);
        float e10 = __expf(s10-m1), e11 = __expf(s11-m1), e12 = __expf(s12-m1);
        float t0 = e00+e01+e02, t1 = e10+e11+e12;
        #pragma unroll
        for (int off = 16; off > 0; off >>= 1) {
            t0 += __shfl_xor_sync(0xffffffffu, t0, off);
            t1 += __shfl_xor_sync(0xffffffffu, t1, off);
        }
        float i0 = 1.f/t0, i1 = 1.f/t1;
        if (v0) {
            float* o = aout + (((size_t)(n*8 + head))*LL + l0)*96;
            o[lane] = e00*i0; o[lane+32] = e01*i0; o[lane+64] = e02*i0;
        }
        if (v1) {
            float* o = aout + (((size_t)(n*8 + head))*LL + l1)*96;
            o[lane] = e10*i1; o[lane+32] = e11*i1; o[lane+64] = e12*i1;
        }
    }
}

// ---------------------------------------------------------------------------
// K5: attend (unchanged from round 5).
// ---------------------------------------------------------------------------
#define VS_STR  100
#define AR_STR  104
#define AC_STR  97
#define SLAB_F  3200

__global__ void __launch_bounds__(256) attend_tf32_kernel(const float* __restrict__ arow,
                                                          const float* __restrict__ acol,
                                                          const float* __restrict__ vpt,
                                                          float* __restrict__ attn)
{
    extern __shared__ float sm[];
    float* vs     = sm;
    float* arow_s = sm + 12800;
    float* acol_s = sm + 12800 + 6656;
    float* red    = vs;

    int lt = blockIdx.x, e = blockIdx.y, n = blockIdx.z;
    int tid = threadIdx.x, lane = tid & 31, wid = tid >> 5;
    int wm = wid & 3, kh = wid >> 2;
    int l0 = lt * 64;
    int r4 = lane >> 2, j = lane & 3;

    uint32_t vs_u = (uint32_t)__cvta_generic_to_shared(vs);
    const float* vbase = vpt + ((size_t)(n*96)*8 + e) * 3072;

    size_t abase = ((size_t)(n*8 + e)) * LL * 96;
    for (int i = tid; i < 64*96; i += 256) {
        int ll = i / 96, x = i - ll*96;
        int lg = l0 + ll;
        float ar = 0.f, ac = 0.f;
        if (lg < LL) {
            ar = arow[abase + (size_t)lg*96 + x];
            ac = acol[abase + (size_t)lg*96 + x];
        }
        int xp = (x & ~7) + ((x & 3) << 1) + ((x >> 2) & 1);
        arow_s[ll*AR_STR + xp] = ar;
        acol_s[ll*AC_STR + x]  = ac;
    }

    #pragma unroll
    for (int t = 0; t < 6; ++t) {
        int cch  = tid + t*256;
        int slab = cch / 768;
        int r    = cch - slab*768;
        int dd   = r / 24;
        int ck   = r - dd*24;
        cp_async16(vs_u + (slab*SLAB_F + dd*VS_STR + ck*4)*4,
                   vbase + (size_t)slab*24576 + dd*96 + ck*4);
    }
    asm volatile("cp.async.commit_group;");

    float c[4][4] = {};

    for (int it = 0; it < 48; ++it) {
        int buf = it & 1;
        if (it + 1 < 48) {
            int nbuf = buf ^ 1;
            #pragma unroll
            for (int t = 0; t < 6; ++t) {
                int cch  = tid + t*256;
                int slab = cch / 768;
                int r    = cch - slab*768;
                int dd   = r / 24;
                int ck   = r - dd*24;
                int h    = (it+1)*2 + slab;
                cp_async16(vs_u + (nbuf*2*SLAB_F + slab*SLAB_F + dd*VS_STR + ck*4)*4,
                           vbase + (size_t)h*24576 + dd*96 + ck*4);
            }
            asm volatile("cp.async.commit_group;");
            asm volatile("cp.async.wait_group 1;");
        } else {
            asm volatile("cp.async.wait_group 0;");
        }
        __syncthreads();

        int h = it*2 + kh;
        const float* vsl = vs + buf*2*SLAB_F + kh*SLAB_F;
        float ac0 = acol_s[(wm*16 +     r4)*AC_STR + h];
        float ac1 = acol_s[(wm*16 + 8 + r4)*AC_STR + h];

        #pragma unroll
        for (int s = 0; s < 12; ++s) {
            uint32_t b[4][2];
            #pragma unroll
            for (int nt = 0; nt < 4; ++nt) {
                b[nt][0] = f2b(vsl[(nt*8 + r4)*VS_STR + s*8 + j]);
                b[nt][1] = f2b(vsl[(nt*8 + r4)*VS_STR + s*8 + j + 4]);
            }
            float2 a0 = *(const float2*)(arow_s + (wm*16 +     r4)*AR_STR + s*8 + j*2);
            float2 a1 = *(const float2*)(arow_s + (wm*16 + 8 + r4)*AR_STR + s*8 + j*2);
            uint32_t a_0 = f2b(cvt_tf32_rna(ac0 * a0.x));
            uint32_t a_1 = f2b(cvt_tf32_rna(ac1 * a1.x));
            uint32_t a_2 = f2b(cvt_tf32_rna(ac0 * a0.y));
            uint32_t a_3 = f2b(cvt_tf32_rna(ac1 * a1.y));
            #pragma unroll
            for (int nt = 0; nt < 4; ++nt)
                mma_tf32(c[nt], a_0, a_1, a_2, a_3, b[nt][0], b[nt][1]);
        }
        __syncthreads();
    }

    if (kh == 1) {
        int rr = wm*16 + r4;
        #pragma unroll
        for (int nt = 0; nt < 4; ++nt) {
            int col = nt*8 + j*2;
            *(float2*)(red + rr*40 + col)     = make_float2(c[nt][0], c[nt][1]);
            *(float2*)(red + (rr+8)*40 + col) = make_float2(c[nt][2], c[nt][3]);
        }
    }
    __syncthreads();
    if (kh == 0) {
        int rr = wm*16 + r4;
        int lg0 = l0 + rr, lg1 = l0 + rr + 8;
        #pragma unroll
        for (int nt = 0; nt < 4; ++nt) {
            int col = nt*8 + j*2;
            float2 r0 = *(const float2*)(red + rr*40 + col);
            float2 r1 = *(const float2*)(red + (rr+8)*40 + col);
            if (lg0 < LL)
                *(float2*)(attn + ((size_t)(lg0*NB + n))*EE + e*HDD + col) =
                    make_float2(c[nt][0] + r0.x, c[nt][1] + r0.y);
            if (lg1 < LL)
                *(float2*)(attn + ((size_t)(lg1*NB + n))*EE + e*HDD + col) =
                    make_float2(c[nt][2] + r1.x, c[nt][3] + r1.y);
        }
    }
}

// ---------------------------------------------------------------------------
// launch
// ---------------------------------------------------------------------------
static inline float* sym_ptr(const void* sym)
{
    void* p = nullptr;
    cudaGetSymbolAddress(&p, sym);
    return (float*)p;
}

extern "C" void kernel_launch(void* const* d_in, const int* in_sizes, int n_in,
                              void* d_out, int out_size)
{
    const float* query_row = (const float*)d_in[0];
    const float* query_col = (const float*)d_in[1];
    const float* key_row   = (const float*)d_in[2];
    const float* key_col   = (const float*)d_in[3];
    const float* value     = (const float*)d_in[4];
    const float* ipw       = (const float*)d_in[5];
    const float* ipb       = (const float*)d_in[6];
    const float* opw       = (const float*)d_in[7];
    const float* opb       = (const float*)d_in[8];
    float* out = (float*)d_out;

    float* krm  = sym_ptr(g_krm);
    float* kcm  = sym_ptr(g_kcm);
    float* qr   = sym_ptr(g_qr);
    float* qc   = sym_ptr(g_qc);
    float* krp  = sym_ptr(g_krp);
    float* kcp  = sym_ptr(g_kcp);
    float* vpt  = sym_ptr(g_vpt);
    float* arow = sym_ptr(g_arow);
    float* acol = sym_ptr(g_acol);
    float* attn = sym_ptr(g_attn);

    const float scale = 0.17677669529663687f;   // 32^-0.5
    const int ATT_SMEM = (12800 + 6656 + 6208) * 4;   // 102656 B

    cudaFuncSetAttribute(attend_tf32_kernel,
                         cudaFuncAttributeMaxDynamicSharedMemorySize, ATT_SMEM);

    // 1. means
    mean_kernel<<<dim3(96, 2, NB), 256>>>(key_row, key_col, krm, kcm);

    // 2a. v projection -> transposed vpt, pre-rounded tf32  (BN=128, pipelined)
    vproj_kernel<<<dim3(2, 576), 256>>>(value, ipw + 4*EE*EE, ipb + 4*EE, vpt);

    // 2b. q/k projections fused (exact hi/lo, pipelined)
    gemm_tf32_multi<<<dim3(4, 50), 256>>>(query_row, query_col, krm, kcm,
                                          qr, qc, krp, kcp, ipw, ipb, scale);

    // 3. scores + softmax
    scores_kernel<<<dim3(NHD, 2, NB*SC_LT), 256>>>(qr, krp, arow, qc, kcp, acol);

    // 4. attend
    attend_tf32_kernel<<<dim3(5, NHD, NB), 256, ATT_SMEM>>>(arow, acol, vpt, attn);

    // 5. out projection -> d_out (rows l*8+n)
    gemm_tf32_kernel<<<dim3(4, 19), 256>>>(attn, opw, opb, out, 2400, 1.f);
}